// round 2
// baseline (speedup 1.0000x reference)
#include <cuda_runtime.h>

// Problem constants
#define BB 32
#define TT 55
#define VV 32000
#define DW 256
#define DD 512
#define AA 200
#define G4 2048   // 4*D

// Scratch (device globals; no allocation allowed)
__device__ float g_w4[BB*TT*G4];     // precomputed w4_all [B,T,4D]
__device__ float g_wr[BB*TT*AA];     // precomputed wr_all [B,T,A]
__device__ float g_h[BB*DD];         // recurrent h state [B,D]
__device__ float g_c[BB*DD];         // cell state
__device__ float g_dt[BB*AA];        // dt state
__device__ float g_gates[BB*G4];     // activated gates for current step
__device__ float g_hall[BB*TT*DD];   // all h_t, [b*T+t, D] for final GEMM

// ---------------------------------------------------------------------------
// Init: h = c = enc_output[:,0,:], dt = act_vecs
// ---------------------------------------------------------------------------
__global__ void init_kernel(const float* __restrict__ enc,
                            const float* __restrict__ act) {
    int i = blockIdx.x * blockDim.x + threadIdx.x;
    if (i < BB*DD) {
        float v = enc[i];
        g_h[i] = v;
        g_c[i] = v;
    } else if (i < BB*DD + BB*AA) {
        g_dt[i - BB*DD] = act[i - BB*DD];
    }
}

// ---------------------------------------------------------------------------
// Generic A@B^T tiled fp32 GEMM: C[M,N] = A[M,K] @ B[N,K]^T + bias[N]
// A rows optionally gathered through idx (embedding lookup).
// Tile 128x128, K-tile 8, 256 threads, 8x8 per thread.
// ---------------------------------------------------------------------------
#define TS 128
#define KT 8

template<bool GATHER>
__global__ void __launch_bounds__(256) gemm_tn(
    int M, int N, int K,
    const float* __restrict__ A, const int* __restrict__ idx,
    const float* __restrict__ B,
    const float* __restrict__ bias,
    float* __restrict__ C, int ldc)
{
    __shared__ float As[KT][TS];
    __shared__ float Bs[KT][TS];

    int tid = threadIdx.x;
    int lrow = tid >> 1;            // 0..127
    int kc   = (tid & 1) * 4;       // 0 or 4

    int gm_l = blockIdx.y * TS + lrow;   // global A row for loading
    int gn_l = blockIdx.x * TS + lrow;   // global B row for loading

    const float* aptr = nullptr;
    if (gm_l < M) {
        int ar = GATHER ? idx[gm_l] : gm_l;
        aptr = A + (size_t)ar * K;
    }
    const float* bptr = (gn_l < N) ? (B + (size_t)gn_l * K) : nullptr;

    int tx = tid & 15;   // 0..15 -> N micro
    int ty = tid >> 4;   // 0..15 -> M micro

    float acc[8][8];
    #pragma unroll
    for (int i = 0; i < 8; i++)
        #pragma unroll
        for (int j = 0; j < 8; j++) acc[i][j] = 0.f;

    for (int k0 = 0; k0 < K; k0 += KT) {
        float4 av = make_float4(0.f, 0.f, 0.f, 0.f);
        float4 bv = make_float4(0.f, 0.f, 0.f, 0.f);
        if (aptr) av = *(const float4*)(aptr + k0 + kc);
        if (bptr) bv = *(const float4*)(bptr + k0 + kc);
        __syncthreads();   // previous compute done before smem overwrite
        As[kc+0][lrow] = av.x; As[kc+1][lrow] = av.y;
        As[kc+2][lrow] = av.z; As[kc+3][lrow] = av.w;
        Bs[kc+0][lrow] = bv.x; Bs[kc+1][lrow] = bv.y;
        Bs[kc+2][lrow] = bv.z; Bs[kc+3][lrow] = bv.w;
        __syncthreads();
        #pragma unroll
        for (int kk = 0; kk < KT; kk++) {
            float4 a0 = *(const float4*)&As[kk][ty*8];
            float4 a1 = *(const float4*)&As[kk][ty*8+4];
            float4 b0 = *(const float4*)&Bs[kk][tx*8];
            float4 b1 = *(const float4*)&Bs[kk][tx*8+4];
            float a[8] = {a0.x,a0.y,a0.z,a0.w,a1.x,a1.y,a1.z,a1.w};
            float b[8] = {b0.x,b0.y,b0.z,b0.w,b1.x,b1.y,b1.z,b1.w};
            #pragma unroll
            for (int i = 0; i < 8; i++)
                #pragma unroll
                for (int j = 0; j < 8; j++)
                    acc[i][j] += a[i] * b[j];
        }
    }

    #pragma unroll
    for (int i = 0; i < 8; i++) {
        int gm = blockIdx.y * TS + ty*8 + i;
        if (gm < M) {
            #pragma unroll
            for (int j = 0; j < 8; j += 4) {
                int gn = blockIdx.x * TS + tx*8 + j;
                if (gn < N) {   // all N used are multiples of 4 -> float4-safe
                    float4 bs = *(const float4*)(bias + gn);
                    float4 o;
                    o.x = acc[i][j+0] + bs.x;
                    o.y = acc[i][j+1] + bs.y;
                    o.z = acc[i][j+2] + bs.z;
                    o.w = acc[i][j+3] + bs.w;
                    *(float4*)(C + (size_t)gm * ldc + gn) = o;
                }
            }
        }
    }
}

// ---------------------------------------------------------------------------
// Phase 1 (per step t): gates g = act(w4 + h@W_h2h^T + b_h2h),
//                       r = sigmoid(wr + h@W_h2h_r^T + b_h2h_r), dt *= r
// Mapping: lane = batch (B==32). Each warp computes 2 output columns:
//   warps [0,1024): g columns;  warps [1024,1124): r columns.
// ---------------------------------------------------------------------------
__device__ __forceinline__ float sigmoidf_(float x) {
    return 1.f / (1.f + expf(-x));
}

__global__ void phase1_kernel(int t,
    const float* __restrict__ Wh2h,  const float* __restrict__ bh2h,
    const float* __restrict__ Wh2hr, const float* __restrict__ bh2hr)
{
    int wid  = (blockIdx.x * blockDim.x + threadIdx.x) >> 5;
    int lane = threadIdx.x & 31;     // == batch index
    const float* hrow = g_h + lane * DD;

    if (wid < 1024) {
        int j0 = wid * 2, j1 = j0 + 1;
        const float* w0 = Wh2h + (size_t)j0 * DD;
        const float* w1 = Wh2h + (size_t)j1 * DD;
        float acc0 = 0.f, acc1 = 0.f;
        #pragma unroll 8
        for (int k = 0; k < DD; k += 4) {
            float4 hv = *(const float4*)(hrow + k);
            float4 a  = *(const float4*)(w0 + k);
            float4 b  = *(const float4*)(w1 + k);
            acc0 += hv.x*a.x + hv.y*a.y + hv.z*a.z + hv.w*a.w;
            acc1 += hv.x*b.x + hv.y*b.y + hv.z*b.z + hv.w*b.w;
        }
        const float* w4r = g_w4 + (size_t)(lane * TT + t) * G4;
        float v0 = w4r[j0] + acc0 + bh2h[j0];
        float v1 = w4r[j1] + acc1 + bh2h[j1];
        v0 = (j0 < 3*DD) ? sigmoidf_(v0) : tanhf(v0);
        v1 = (j1 < 3*DD) ? sigmoidf_(v1) : tanhf(v1);
        g_gates[lane * G4 + j0] = v0;
        g_gates[lane * G4 + j1] = v1;
    } else if (wid < 1124) {
        int a0 = (wid - 1024) * 2, a1 = a0 + 1;
        const float* w0 = Wh2hr + (size_t)a0 * DD;
        const float* w1 = Wh2hr + (size_t)a1 * DD;
        float acc0 = 0.f, acc1 = 0.f;
        #pragma unroll 8
        for (int k = 0; k < DD; k += 4) {
            float4 hv = *(const float4*)(hrow + k);
            float4 a  = *(const float4*)(w0 + k);
            float4 b  = *(const float4*)(w1 + k);
            acc0 += hv.x*a.x + hv.y*a.y + hv.z*a.z + hv.w*a.w;
            acc1 += hv.x*b.x + hv.y*b.y + hv.z*b.z + hv.w*b.w;
        }
        const float* wrr = g_wr + (size_t)(lane * TT + t) * AA;
        float r0 = sigmoidf_(wrr[a0] + acc0 + bh2hr[a0]);
        float r1 = sigmoidf_(wrr[a1] + acc1 + bh2hr[a1]);
        g_dt[lane * AA + a0] *= r0;
        g_dt[lane * AA + a1] *= r1;
    }
}

// ---------------------------------------------------------------------------
// Phase 2 (per step t): dtw = tanh(dt@W_dc^T); c = f*c + i*chat + dtw;
//                       h = o*tanh(c); record h into g_hall.
// lane = batch, warp handles 2 of the 512 columns.
// ---------------------------------------------------------------------------
__device__ __forceinline__ void cell_update(int b, int j, float dtw, int t) {
    float gi = g_gates[b * G4 + j];
    float gf = g_gates[b * G4 + DD + j];
    float go = g_gates[b * G4 + 2*DD + j];
    float ch = g_gates[b * G4 + 3*DD + j];
    float c  = gf * g_c[b * DD + j] + gi * ch + dtw;
    float h  = go * tanhf(c);
    g_c[b * DD + j] = c;
    g_h[b * DD + j] = h;
    g_hall[(size_t)(b * TT + t) * DD + j] = h;
}

__global__ void phase2_kernel(int t, const float* __restrict__ Wdc)
{
    int wid  = (blockIdx.x * blockDim.x + threadIdx.x) >> 5;
    int lane = threadIdx.x & 31;     // == batch index
    if (wid >= 256) return;
    int j0 = wid * 2, j1 = j0 + 1;
    const float* dtr = g_dt + lane * AA;
    const float* w0  = Wdc + (size_t)j0 * AA;
    const float* w1  = Wdc + (size_t)j1 * AA;
    float acc0 = 0.f, acc1 = 0.f;
    #pragma unroll 10
    for (int a = 0; a < AA; a += 4) {
        float4 dv = *(const float4*)(dtr + a);
        float4 a4 = *(const float4*)(w0 + a);
        float4 b4 = *(const float4*)(w1 + a);
        acc0 += dv.x*a4.x + dv.y*a4.y + dv.z*a4.z + dv.w*a4.w;
        acc1 += dv.x*b4.x + dv.y*b4.y + dv.z*b4.z + dv.w*b4.w;
    }
    cell_update(lane, j0, tanhf(acc0), t);
    cell_update(lane, j1, tanhf(acc1), t);
}

// ---------------------------------------------------------------------------
// Launch
// ---------------------------------------------------------------------------
extern "C" void kernel_launch(void* const* d_in, const int* in_sizes, int n_in,
                              void* d_out, int out_size) {
    const int*   tgt   = (const int*)  d_in[0];
    const float* enc   = (const float*)d_in[1];
    const float* act   = (const float*)d_in[2];
    const float* E     = (const float*)d_in[3];
    const float* Ww2h  = (const float*)d_in[4];
    const float* bw2h  = (const float*)d_in[5];
    const float* Wh2h  = (const float*)d_in[6];
    const float* bh2h  = (const float*)d_in[7];
    const float* Ww2hr = (const float*)d_in[8];
    const float* bw2hr = (const float*)d_in[9];
    const float* Wh2hr = (const float*)d_in[10];
    const float* bh2hr = (const float*)d_in[11];
    const float* Wdc   = (const float*)d_in[12];
    const float* Wout  = (const float*)d_in[13];
    const float* bout  = (const float*)d_in[14];
    float* out = (float*)d_out;

    float *pw4, *pwr, *phall;
    cudaGetSymbolAddress((void**)&pw4,   g_w4);
    cudaGetSymbolAddress((void**)&pwr,   g_wr);
    cudaGetSymbolAddress((void**)&phall, g_hall);

    // state init
    {
        int n = BB*DD + BB*AA;
        init_kernel<<<(n + 255) / 256, 256>>>(enc, act);
    }

    // precompute w4_all and wr_all (embedding gather fused into GEMM)
    {
        dim3 g1((G4 + TS - 1) / TS, (BB*TT + TS - 1) / TS);   // 16 x 14
        gemm_tn<true><<<g1, 256>>>(BB*TT, G4, DW, E, tgt, Ww2h, bw2h, pw4, G4);
        dim3 g2((AA + TS - 1) / TS, (BB*TT + TS - 1) / TS);   // 2 x 14
        gemm_tn<true><<<g2, 256>>>(BB*TT, AA, DW, E, tgt, Ww2hr, bw2hr, pwr, AA);
    }

    // sequential recurrence: 55 steps x 2 kernels
    for (int t = 0; t < TT; t++) {
        phase1_kernel<<<141, 256>>>(t, Wh2h, bh2h, Wh2hr, bh2hr);
        phase2_kernel<<<32, 256>>>(t, Wdc);
    }

    // dominant output projection: out[b*T+t, v] = h_all . W_out[v] + b_out[v]
    {
        dim3 g3(VV / TS, (BB*TT + TS - 1) / TS);   // 250 x 14
        gemm_tn<false><<<g3, 256>>>(BB*TT, VV, DD, phall, nullptr, Wout, bout,
                                    out, VV);
    }
}

// round 4
// speedup vs baseline: 1.2624x; 1.2624x over previous
#include <cuda_runtime.h>
#include <math.h>

// Problem constants
#define BB 32
#define TT 55
#define VV 32000
#define DW 256
#define DD 512
#define AA 200
#define G4 2048   // 4*D

#define NB   148   // persistent blocks (<= SM count, all co-resident)
#define NTHR 256

// Scratch (device globals; no allocation allowed)
__device__ float g_w4[BB*TT*G4];     // precomputed w4_all [b*T+t, 4D]
__device__ float g_wr[BB*TT*AA];     // precomputed wr_all [b*T+t, A]
__device__ float g_h[BB*DD];         // recurrent h state [B,D]
__device__ float g_dt[BB*AA];        // dt state (mirrored from registers)
__device__ float g_gates[BB*G4];     // activated gates for current step
__device__ float g_hall[BB*TT*DD];   // all h_t, [b*T+t, D] for final GEMM
__device__ unsigned g_barcnt;        // grid barrier counter (monotonic)

// ---------------------------------------------------------------------------
__global__ void init_kernel(const float* __restrict__ enc) {
    int i = blockIdx.x * blockDim.x + threadIdx.x;
    if (i < BB*DD) g_h[i] = enc[i];
    if (i == 0) g_barcnt = 0u;
}

__device__ __forceinline__ float sigmoidf_(float x) {
    return 1.f / (1.f + expf(-x));
}

// Grid barrier: CTA barrier elevates all threads' stores, thread0 does
// gpu-scope fence + arrive, spins on monotonic counter, acquire-fence,
// CTA barrier broadcasts.
__device__ __forceinline__ void gridbar(unsigned tgt) {
    __syncthreads();
    if (threadIdx.x == 0) {
        __threadfence();
        atomicAdd(&g_barcnt, 1u);
        while (*((volatile unsigned*)&g_barcnt) < tgt) { }
        __threadfence();
    }
    __syncthreads();
}

// ---------------------------------------------------------------------------
// Persistent recurrence kernel.
// Phase1 (per step): gates = act(w4 + h@W_h2h^T + b), r = sigm(wr + h@W_h2h_r^T + b),
//                    dt *= r  (dt held in registers by owner threads)
//   Mapping: 2248 output cols in 71 groups of 32; lane = col-in-group,
//   warp = 2 batches; block = (colgroup, batch-half). 142 working blocks.
//   Weight rows are fixed per lane across all 55 steps -> L1-resident.
// Phase2 (per step): dtw = tanh(dt@W_dc^T); c = f*c + i*chat + dtw (c in regs);
//                    h = o*tanh(c); h -> g_h and g_hall.
//   Mapping: blk<64: colgroup = blk>>2 (16 groups), batch = (blk&3)*8 + warp.
// ---------------------------------------------------------------------------
__global__ void __launch_bounds__(NTHR, 1) recurrent_kernel(
    const float* __restrict__ Wh2h,  const float* __restrict__ bh2h,
    const float* __restrict__ Wh2hr, const float* __restrict__ bh2hr,
    const float* __restrict__ Wdc,
    const float* __restrict__ enc,   const float* __restrict__ act)
{
    __shared__ float hs[16 * DD];    // 32 KB: this block's 16 batch rows of h

    const int blk  = blockIdx.x;
    const int tid  = threadIdx.x;
    const int w    = tid >> 5;
    const int lane = tid & 31;

    // ---- phase1 task setup (fixed for whole kernel) ----
    const int  task = blk;                 // valid if < 142
    const int  colg = task >> 1;
    const int  bh   = task & 1;
    const int  col  = colg * 32 + lane;    // 0..2271
    const bool p1   = (task < 142) && (col < G4 + AA);
    const int  b0   = bh * 16 + w * 2;
    const int  b1   = b0 + 1;

    const float* Wrow = nullptr;
    float bias = 0.f;
    bool  is_r = false;
    int   acol = 0;
    if (p1) {
        if (col < G4) { Wrow = Wh2h + (size_t)col * DD; bias = bh2h[col]; }
        else { is_r = true; acol = col - G4;
               Wrow = Wh2hr + (size_t)acol * DD; bias = bh2hr[acol]; }
    }
    // dt state in registers for r-owner threads
    float d0 = 0.f, d1 = 0.f;
    if (p1 && is_r) {
        d0 = __ldcg(act + b0 * AA + acol);
        d1 = __ldcg(act + b1 * AA + acol);
    }

    // ---- phase2 task setup ----
    const bool p2 = (blk < 64);
    const int  colg2 = blk >> 2;              // 0..15
    const int  b2    = (blk & 3) * 8 + w;     // 0..31
    const int  j2    = colg2 * 32 + lane;     // 0..511
    const float* WdcRow = Wdc + (size_t)j2 * AA;
    float creg = 0.f;
    if (p2) creg = __ldcg(enc + b2 * DD + j2);   // c0 = h0 = enc row

    unsigned tgt = NB;

    for (int t = 0; t < TT; t++) {
        // ---- stage h[bh*16 .. bh*16+15][:] into smem (coalesced, L1-bypass) ----
        if (task < 142) {
            const float4* src = (const float4*)(g_h + bh * 16 * DD);
            float4* dst = (float4*)hs;
            #pragma unroll
            for (int i = 0; i < (16 * DD / 4) / NTHR; i++)
                dst[i * NTHR + tid] = __ldcg(src + i * NTHR + tid);
        }
        __syncthreads();

        // ---- phase1 compute ----
        if (p1) {
            const float4* h0 = (const float4*)(hs + (w * 2)     * DD);
            const float4* h1 = (const float4*)(hs + (w * 2 + 1) * DD);
            const float4* wp = (const float4*)Wrow;
            float acc0 = 0.f, acc1 = 0.f;
            #pragma unroll 8
            for (int k = 0; k < DD / 4; k++) {
                float4 wv = wp[k];            // L1-resident after step 0
                float4 a  = h0[k];            // smem broadcast
                float4 b  = h1[k];
                acc0 += wv.x*a.x + wv.y*a.y + wv.z*a.z + wv.w*a.w;
                acc1 += wv.x*b.x + wv.y*b.y + wv.z*b.z + wv.w*b.w;
            }
            if (!is_r) {
                float v0 = g_w4[(size_t)(b0*TT + t) * G4 + col] + acc0 + bias;
                float v1 = g_w4[(size_t)(b1*TT + t) * G4 + col] + acc1 + bias;
                v0 = (col < 3*DD) ? sigmoidf_(v0) : tanhf(v0);
                v1 = (col < 3*DD) ? sigmoidf_(v1) : tanhf(v1);
                g_gates[b0 * G4 + col] = v0;
                g_gates[b1 * G4 + col] = v1;
            } else {
                float r0 = sigmoidf_(g_wr[(size_t)(b0*TT + t) * AA + acol] + acc0 + bias);
                float r1 = sigmoidf_(g_wr[(size_t)(b1*TT + t) * AA + acol] + acc1 + bias);
                d0 *= r0;
                d1 *= r1;
                g_dt[b0 * AA + acol] = d0;
                g_dt[b1 * AA + acol] = d1;
            }
        }

        gridbar(tgt); tgt += NB;   // gates + dt complete

        // ---- phase2 compute ----
        if (p2) {
            const float4* dtp = (const float4*)(g_dt + b2 * AA);
            const float4* wp  = (const float4*)WdcRow;
            float acc = 0.f;
            #pragma unroll
            for (int k = 0; k < AA / 4; k++) {
                float4 dv = __ldcg(dtp + k);  // warp-uniform broadcast, L2
                float4 wv = wp[k];            // L1-resident after step 0
                acc += wv.x*dv.x + wv.y*dv.y + wv.z*dv.z + wv.w*dv.w;
            }
            float dtw = tanhf(acc);
            float gi = __ldcg(g_gates + b2 * G4 + j2);
            float gf = __ldcg(g_gates + b2 * G4 + DD   + j2);
            float go = __ldcg(g_gates + b2 * G4 + 2*DD + j2);
            float ch = __ldcg(g_gates + b2 * G4 + 3*DD + j2);
            creg = gf * creg + gi * ch + dtw;
            float h = go * tanhf(creg);
            g_h[b2 * DD + j2] = h;
            g_hall[(size_t)(b2 * TT + t) * DD + j2] = h;
        }

        gridbar(tgt); tgt += NB;   // h complete for next step
    }
}

// ---------------------------------------------------------------------------
// Generic A@B^T tiled fp32 GEMM: C[M,N] = A[M,K] @ B[N,K]^T + bias[N]
// A rows optionally gathered through idx (embedding lookup).
// Tile 128x128, K-tile 8, 256 threads, 8x8 per thread.
// ---------------------------------------------------------------------------
#define TS 128
#define KT 8

template<bool GATHER>
__global__ void __launch_bounds__(256) gemm_tn(
    int M, int N, int K,
    const float* __restrict__ A, const int* __restrict__ idx,
    const float* __restrict__ B,
    const float* __restrict__ bias,
    float* __restrict__ C, int ldc)
{
    __shared__ float As[KT][TS];
    __shared__ float Bs[KT][TS];

    int tid = threadIdx.x;
    int lrow = tid >> 1;            // 0..127
    int kc   = (tid & 1) * 4;       // 0 or 4

    int gm_l = blockIdx.y * TS + lrow;   // global A row for loading
    int gn_l = blockIdx.x * TS + lrow;   // global B row for loading

    const float* aptr = nullptr;
    if (gm_l < M) {
        int ar = GATHER ? idx[gm_l] : gm_l;
        aptr = A + (size_t)ar * K;
    }
    const float* bptr = (gn_l < N) ? (B + (size_t)gn_l * K) : nullptr;

    int tx = tid & 15;   // 0..15 -> N micro
    int ty = tid >> 4;   // 0..15 -> M micro

    float acc[8][8];
    #pragma unroll
    for (int i = 0; i < 8; i++)
        #pragma unroll
        for (int j = 0; j < 8; j++) acc[i][j] = 0.f;

    for (int k0 = 0; k0 < K; k0 += KT) {
        float4 av = make_float4(0.f, 0.f, 0.f, 0.f);
        float4 bv = make_float4(0.f, 0.f, 0.f, 0.f);
        if (aptr) av = *(const float4*)(aptr + k0 + kc);
        if (bptr) bv = *(const float4*)(bptr + k0 + kc);
        __syncthreads();   // previous compute done before smem overwrite
        As[kc+0][lrow] = av.x; As[kc+1][lrow] = av.y;
        As[kc+2][lrow] = av.z; As[kc+3][lrow] = av.w;
        Bs[kc+0][lrow] = bv.x; Bs[kc+1][lrow] = bv.y;
        Bs[kc+2][lrow] = bv.z; Bs[kc+3][lrow] = bv.w;
        __syncthreads();
        #pragma unroll
        for (int kk = 0; kk < KT; kk++) {
            float4 a0 = *(const float4*)&As[kk][ty*8];
            float4 a1 = *(const float4*)&As[kk][ty*8+4];
            float4 b0 = *(const float4*)&Bs[kk][tx*8];
            float4 b1 = *(const float4*)&Bs[kk][tx*8+4];
            float a[8] = {a0.x,a0.y,a0.z,a0.w,a1.x,a1.y,a1.z,a1.w};
            float b[8] = {b0.x,b0.y,b0.z,b0.w,b1.x,b1.y,b1.z,b1.w};
            #pragma unroll
            for (int i = 0; i < 8; i++)
                #pragma unroll
                for (int j = 0; j < 8; j++)
                    acc[i][j] += a[i] * b[j];
        }
    }

    #pragma unroll
    for (int i = 0; i < 8; i++) {
        int gm = blockIdx.y * TS + ty*8 + i;
        if (gm < M) {
            #pragma unroll
            for (int j = 0; j < 8; j += 4) {
                int gn = blockIdx.x * TS + tx*8 + j;
                if (gn < N) {   // all N used are multiples of 4 -> float4-safe
                    float4 bs = *(const float4*)(bias + gn);
                    float4 o;
                    o.x = acc[i][j+0] + bs.x;
                    o.y = acc[i][j+1] + bs.y;
                    o.z = acc[i][j+2] + bs.z;
                    o.w = acc[i][j+3] + bs.w;
                    *(float4*)(C + (size_t)gm * ldc + gn) = o;
                }
            }
        }
    }
}

// ---------------------------------------------------------------------------
// Launch
// ---------------------------------------------------------------------------
extern "C" void kernel_launch(void* const* d_in, const int* in_sizes, int n_in,
                              void* d_out, int out_size) {
    const int*   tgt   = (const int*)  d_in[0];
    const float* enc   = (const float*)d_in[1];
    const float* act   = (const float*)d_in[2];
    const float* E     = (const float*)d_in[3];
    const float* Ww2h  = (const float*)d_in[4];
    const float* bw2h  = (const float*)d_in[5];
    const float* Wh2h  = (const float*)d_in[6];
    const float* bh2h  = (const float*)d_in[7];
    const float* Ww2hr = (const float*)d_in[8];
    const float* bw2hr = (const float*)d_in[9];
    const float* Wh2hr = (const float*)d_in[10];
    const float* bh2hr = (const float*)d_in[11];
    const float* Wdc   = (const float*)d_in[12];
    const float* Wout  = (const float*)d_in[13];
    const float* bout  = (const float*)d_in[14];
    float* out = (float*)d_out;

    float *pw4, *pwr, *phall;
    cudaGetSymbolAddress((void**)&pw4,   g_w4);
    cudaGetSymbolAddress((void**)&pwr,   g_wr);
    cudaGetSymbolAddress((void**)&phall, g_hall);

    // state init (h = enc, barrier counter = 0)
    init_kernel<<<(BB*DD + 255) / 256, 256>>>(enc);

    // precompute w4_all and wr_all (embedding gather fused into GEMM)
    {
        dim3 g1((G4 + TS - 1) / TS, (BB*TT + TS - 1) / TS);   // 16 x 14
        gemm_tn<true><<<g1, 256>>>(BB*TT, G4, DW, E, tgt, Ww2h, bw2h, pw4, G4);
        dim3 g2((AA + TS - 1) / TS, (BB*TT + TS - 1) / TS);   // 2 x 14
        gemm_tn<true><<<g2, 256>>>(BB*TT, AA, DW, E, tgt, Ww2hr, bw2hr, pwr, AA);
    }

    // whole recurrence in ONE persistent kernel
    recurrent_kernel<<<NB, NTHR>>>(Wh2h, bh2h, Wh2hr, bh2hr, Wdc, enc, act);

    // dominant output projection: out[b*T+t, v] = h_all . W_out[v] + b_out[v]
    {
        dim3 g3(VV / TS, (BB*TT + TS - 1) / TS);   // 250 x 14
        gemm_tn<false><<<g3, 256>>>(BB*TT, VV, DD, phall, nullptr, Wout, bout,
                                    out, VV);
    }
}

// round 5
// speedup vs baseline: 1.8134x; 1.4365x over previous
#include <cuda_runtime.h>
#include <math.h>

// Problem constants
#define BB 32
#define TT 55
#define VV 32000
#define DW 256
#define DD 512
#define AA 200
#define G4 2048   // 4*D

#define NB   148   // persistent blocks (<= SM count, all co-resident)
#define NTHR 256

// Scratch (device globals; no allocation allowed)
__device__ float g_w4[BB*TT*G4];     // precomputed w4_all [b*T+t, 4D]
__device__ float g_wr[BB*TT*AA];     // precomputed wr_all [b*T+t, A]
__device__ float g_h[BB*DD];         // recurrent h state [B,D]
__device__ float g_dt[BB*AA];        // dt state (mirrored from registers)
__device__ float g_gates[BB*G4];     // activated gates for current step
__device__ float g_hall[BB*TT*DD];   // all h_t, [b*T+t, D] for final GEMM
__device__ unsigned g_barcnt;        // grid barrier counter (monotonic)

// ---------------------------------------------------------------------------
__global__ void init_kernel(const float* __restrict__ enc) {
    int i = blockIdx.x * blockDim.x + threadIdx.x;
    if (i < BB*DD) g_h[i] = enc[i];
    if (i == 0) g_barcnt = 0u;
}

__device__ __forceinline__ float sigmoidf_(float x) {
    return 1.f / (1.f + expf(-x));
}

// Grid barrier
__device__ __forceinline__ void gridbar(unsigned tgt) {
    __syncthreads();
    if (threadIdx.x == 0) {
        __threadfence();
        atomicAdd(&g_barcnt, 1u);
        while (*((volatile unsigned*)&g_barcnt) < tgt) { }
        __threadfence();
    }
    __syncthreads();
}

// ---------------------------------------------------------------------------
// Persistent recurrence kernel (unchanged from R4 — measured win).
// ---------------------------------------------------------------------------
__global__ void __launch_bounds__(NTHR, 1) recurrent_kernel(
    const float* __restrict__ Wh2h,  const float* __restrict__ bh2h,
    const float* __restrict__ Wh2hr, const float* __restrict__ bh2hr,
    const float* __restrict__ Wdc,
    const float* __restrict__ enc,   const float* __restrict__ act)
{
    __shared__ float hs[16 * DD];    // 32 KB: this block's 16 batch rows of h

    const int blk  = blockIdx.x;
    const int tid  = threadIdx.x;
    const int w    = tid >> 5;
    const int lane = tid & 31;

    // ---- phase1 task setup ----
    const int  task = blk;                 // valid if < 142
    const int  colg = task >> 1;
    const int  bh   = task & 1;
    const int  col  = colg * 32 + lane;    // 0..2271
    const bool p1   = (task < 142) && (col < G4 + AA);
    const int  b0   = bh * 16 + w * 2;
    const int  b1   = b0 + 1;

    const float* Wrow = nullptr;
    float bias = 0.f;
    bool  is_r = false;
    int   acol = 0;
    if (p1) {
        if (col < G4) { Wrow = Wh2h + (size_t)col * DD; bias = bh2h[col]; }
        else { is_r = true; acol = col - G4;
               Wrow = Wh2hr + (size_t)acol * DD; bias = bh2hr[acol]; }
    }
    float d0 = 0.f, d1 = 0.f;
    if (p1 && is_r) {
        d0 = __ldcg(act + b0 * AA + acol);
        d1 = __ldcg(act + b1 * AA + acol);
    }

    // ---- phase2 task setup ----
    const bool p2 = (blk < 64);
    const int  colg2 = blk >> 2;              // 0..15
    const int  b2    = (blk & 3) * 8 + w;     // 0..31
    const int  j2    = colg2 * 32 + lane;     // 0..511
    const float* WdcRow = Wdc + (size_t)j2 * AA;
    float creg = 0.f;
    if (p2) creg = __ldcg(enc + b2 * DD + j2);   // c0 = h0 = enc row

    unsigned tgt = NB;

    for (int t = 0; t < TT; t++) {
        if (task < 142) {
            const float4* src = (const float4*)(g_h + bh * 16 * DD);
            float4* dst = (float4*)hs;
            #pragma unroll
            for (int i = 0; i < (16 * DD / 4) / NTHR; i++)
                dst[i * NTHR + tid] = __ldcg(src + i * NTHR + tid);
        }
        __syncthreads();

        if (p1) {
            const float4* h0 = (const float4*)(hs + (w * 2)     * DD);
            const float4* h1 = (const float4*)(hs + (w * 2 + 1) * DD);
            const float4* wp = (const float4*)Wrow;
            float acc0 = 0.f, acc1 = 0.f;
            #pragma unroll 8
            for (int k = 0; k < DD / 4; k++) {
                float4 wv = wp[k];
                float4 a  = h0[k];
                float4 b  = h1[k];
                acc0 += wv.x*a.x + wv.y*a.y + wv.z*a.z + wv.w*a.w;
                acc1 += wv.x*b.x + wv.y*b.y + wv.z*b.z + wv.w*b.w;
            }
            if (!is_r) {
                float v0 = g_w4[(size_t)(b0*TT + t) * G4 + col] + acc0 + bias;
                float v1 = g_w4[(size_t)(b1*TT + t) * G4 + col] + acc1 + bias;
                v0 = (col < 3*DD) ? sigmoidf_(v0) : tanhf(v0);
                v1 = (col < 3*DD) ? sigmoidf_(v1) : tanhf(v1);
                g_gates[b0 * G4 + col] = v0;
                g_gates[b1 * G4 + col] = v1;
            } else {
                float r0 = sigmoidf_(g_wr[(size_t)(b0*TT + t) * AA + acol] + acc0 + bias);
                float r1 = sigmoidf_(g_wr[(size_t)(b1*TT + t) * AA + acol] + acc1 + bias);
                d0 *= r0;
                d1 *= r1;
                g_dt[b0 * AA + acol] = d0;
                g_dt[b1 * AA + acol] = d1;
            }
        }

        gridbar(tgt); tgt += NB;

        if (p2) {
            const float4* dtp = (const float4*)(g_dt + b2 * AA);
            const float4* wp  = (const float4*)WdcRow;
            float acc = 0.f;
            #pragma unroll
            for (int k = 0; k < AA / 4; k++) {
                float4 dv = __ldcg(dtp + k);
                float4 wv = wp[k];
                acc += wv.x*dv.x + wv.y*dv.y + wv.z*dv.z + wv.w*dv.w;
            }
            float dtw = tanhf(acc);
            float gi = __ldcg(g_gates + b2 * G4 + j2);
            float gf = __ldcg(g_gates + b2 * G4 + DD   + j2);
            float go = __ldcg(g_gates + b2 * G4 + 2*DD + j2);
            float ch = __ldcg(g_gates + b2 * G4 + 3*DD + j2);
            creg = gf * creg + gi * ch + dtw;
            float h = go * tanhf(creg);
            g_h[b2 * DD + j2] = h;
            g_hall[(size_t)(b2 * TT + t) * DD + j2] = h;
        }

        gridbar(tgt); tgt += NB;
    }
}

// ---------------------------------------------------------------------------
// fp32 tiled GEMM (kept for the two small precompute GEMMs)
// ---------------------------------------------------------------------------
#define TS 128
#define KT 8

template<bool GATHER>
__global__ void __launch_bounds__(256) gemm_tn(
    int M, int N, int K,
    const float* __restrict__ A, const int* __restrict__ idx,
    const float* __restrict__ B,
    const float* __restrict__ bias,
    float* __restrict__ C, int ldc)
{
    __shared__ float As[KT][TS];
    __shared__ float Bs[KT][TS];

    int tid = threadIdx.x;
    int lrow = tid >> 1;
    int kc   = (tid & 1) * 4;

    int gm_l = blockIdx.y * TS + lrow;
    int gn_l = blockIdx.x * TS + lrow;

    const float* aptr = nullptr;
    if (gm_l < M) {
        int ar = GATHER ? idx[gm_l] : gm_l;
        aptr = A + (size_t)ar * K;
    }
    const float* bptr = (gn_l < N) ? (B + (size_t)gn_l * K) : nullptr;

    int tx = tid & 15;
    int ty = tid >> 4;

    float acc[8][8];
    #pragma unroll
    for (int i = 0; i < 8; i++)
        #pragma unroll
        for (int j = 0; j < 8; j++) acc[i][j] = 0.f;

    for (int k0 = 0; k0 < K; k0 += KT) {
        float4 av = make_float4(0.f, 0.f, 0.f, 0.f);
        float4 bv = make_float4(0.f, 0.f, 0.f, 0.f);
        if (aptr) av = *(const float4*)(aptr + k0 + kc);
        if (bptr) bv = *(const float4*)(bptr + k0 + kc);
        __syncthreads();
        As[kc+0][lrow] = av.x; As[kc+1][lrow] = av.y;
        As[kc+2][lrow] = av.z; As[kc+3][lrow] = av.w;
        Bs[kc+0][lrow] = bv.x; Bs[kc+1][lrow] = bv.y;
        Bs[kc+2][lrow] = bv.z; Bs[kc+3][lrow] = bv.w;
        __syncthreads();
        #pragma unroll
        for (int kk = 0; kk < KT; kk++) {
            float4 a0 = *(const float4*)&As[kk][ty*8];
            float4 a1 = *(const float4*)&As[kk][ty*8+4];
            float4 b0 = *(const float4*)&Bs[kk][tx*8];
            float4 b1 = *(const float4*)&Bs[kk][tx*8+4];
            float a[8] = {a0.x,a0.y,a0.z,a0.w,a1.x,a1.y,a1.z,a1.w};
            float b[8] = {b0.x,b0.y,b0.z,b0.w,b1.x,b1.y,b1.z,b1.w};
            #pragma unroll
            for (int i = 0; i < 8; i++)
                #pragma unroll
                for (int j = 0; j < 8; j++)
                    acc[i][j] += a[i] * b[j];
        }
    }

    #pragma unroll
    for (int i = 0; i < 8; i++) {
        int gm = blockIdx.y * TS + ty*8 + i;
        if (gm < M) {
            #pragma unroll
            for (int j = 0; j < 8; j += 4) {
                int gn = blockIdx.x * TS + tx*8 + j;
                if (gn < N) {
                    float4 bs = *(const float4*)(bias + gn);
                    float4 o;
                    o.x = acc[i][j+0] + bs.x;
                    o.y = acc[i][j+1] + bs.y;
                    o.z = acc[i][j+2] + bs.z;
                    o.w = acc[i][j+3] + bs.w;
                    *(float4*)(C + (size_t)gm * ldc + gn) = o;
                }
            }
        }
    }
}

// ---------------------------------------------------------------------------
// tf32 tensor-core GEMM: C[M,N] = A[M,K] @ B[N,K]^T + bias[N]
// CTA 128x128, K-tile 32, 8 warps (warp tile 64x32), m16n8k8 mma, fp32 accum.
// XOR-swizzled smem (rows are exactly 128B), double-buffered.
// Requires: N % 128 == 0, K % 32 == 0 (true: N=32000, K=512).
// ---------------------------------------------------------------------------
#define Bb 128
#define BKt 32

__device__ __forceinline__ unsigned tf32r(float x) {
    unsigned y;
    asm("cvt.rna.tf32.f32 %0, %1;" : "=r"(y) : "f"(x));
    return y;
}

__device__ __forceinline__ void mma_tf32(float c[4],
    unsigned a0, unsigned a1, unsigned a2, unsigned a3,
    unsigned b0, unsigned b1)
{
    asm volatile(
        "mma.sync.aligned.m16n8k8.row.col.f32.tf32.tf32.f32 "
        "{%0,%1,%2,%3}, {%4,%5,%6,%7}, {%8,%9}, {%0,%1,%2,%3};\n"
        : "+f"(c[0]), "+f"(c[1]), "+f"(c[2]), "+f"(c[3])
        : "r"(a0), "r"(a1), "r"(a2), "r"(a3), "r"(b0), "r"(b1));
}

__global__ void __launch_bounds__(256, 1) gemm_tf32(
    int M, int K,
    const float* __restrict__ A,      // [M,K] row-major
    const float* __restrict__ B,      // [N,K] row-major
    const float* __restrict__ bias,   // [N]
    float* __restrict__ C, int ldc)
{
    __shared__ unsigned As[2][BB == 0 ? 1 : 128 * BKt];   // 16KB each
    __shared__ unsigned Bs[2][128 * BKt];

    const int tid  = threadIdx.x;
    const int lane = tid & 31;
    const int w    = tid >> 5;
    const int wm   = (w & 1) * 64;       // warp m offset in tile
    const int wn   = (w >> 1) * 32;      // warp n offset in tile
    const int g8   = lane >> 2;          // 0..7 (row group)
    const int tq   = lane & 3;           // 0..3 (k / col group)

    const int bM = blockIdx.y * 128;
    const int bN = blockIdx.x * 128;

    // global loader mapping: 256 thr, each 4 float4 per operand per k-tile
    const int lrow = tid >> 3;   // 0..31
    const int lf   = tid & 7;    // chunk 0..7 (16B within 128B row)

    float acc[4][4][4];
    #pragma unroll
    for (int mi = 0; mi < 4; mi++)
        #pragma unroll
        for (int ni = 0; ni < 4; ni++)
            #pragma unroll
            for (int q = 0; q < 4; q++) acc[mi][ni][q] = 0.f;

    const int NKT = K / BKt;     // 16
    float4 pa[4], pb[4];

    // prefetch tile 0
    #pragma unroll
    for (int i = 0; i < 4; i++) {
        int r = bM + lrow + 32*i; if (r >= M) r = M - 1;
        pa[i] = *(const float4*)(A + (size_t)r * K + lf*4);
        int rn = bN + lrow + 32*i;
        pb[i] = *(const float4*)(B + (size_t)rn * K + lf*4);
    }
    // store tile 0 (cvt to tf32, swizzled)
    #pragma unroll
    for (int i = 0; i < 4; i++) {
        int r = lrow + 32*i;
        int ch = lf ^ (r & 7);
        uint4 va = make_uint4(tf32r(pa[i].x), tf32r(pa[i].y), tf32r(pa[i].z), tf32r(pa[i].w));
        uint4 vb = make_uint4(tf32r(pb[i].x), tf32r(pb[i].y), tf32r(pb[i].z), tf32r(pb[i].w));
        *(uint4*)&As[0][r*32 + ch*4] = va;
        *(uint4*)&Bs[0][r*32 + ch*4] = vb;
    }
    __syncthreads();

    for (int kt = 0; kt < NKT; kt++) {
        int cur = kt & 1;
        // prefetch next tile into regs
        if (kt + 1 < NKT) {
            #pragma unroll
            for (int i = 0; i < 4; i++) {
                int r = bM + lrow + 32*i; if (r >= M) r = M - 1;
                pa[i] = *(const float4*)(A + (size_t)r * K + (kt+1)*BKt + lf*4);
                int rn = bN + lrow + 32*i;
                pb[i] = *(const float4*)(B + (size_t)rn * K + (kt+1)*BKt + lf*4);
            }
        }

        // compute 4 k8-slices of current tile
        const unsigned* sA = As[cur];
        const unsigned* sB = Bs[cur];
        #pragma unroll
        for (int s = 0; s < 4; s++) {
            const int c0 = s*2;        // 16B chunk of k8..k8+3
            const int c1 = s*2 + 1;    // chunk of k8+4..k8+7
            unsigned af[4][4];
            #pragma unroll
            for (int mi = 0; mi < 4; mi++) {
                int r0 = wm + mi*16 + g8;
                int r1 = r0 + 8;
                af[mi][0] = sA[r0*32 + (c0 ^ (r0 & 7))*4 + tq];
                af[mi][1] = sA[r1*32 + (c0 ^ (r1 & 7))*4 + tq];
                af[mi][2] = sA[r0*32 + (c1 ^ (r0 & 7))*4 + tq];
                af[mi][3] = sA[r1*32 + (c1 ^ (r1 & 7))*4 + tq];
            }
            unsigned bf[4][2];
            #pragma unroll
            for (int ni = 0; ni < 4; ni++) {
                int n0 = wn + ni*8 + g8;
                bf[ni][0] = sB[n0*32 + (c0 ^ (n0 & 7))*4 + tq];
                bf[ni][1] = sB[n0*32 + (c1 ^ (n0 & 7))*4 + tq];
            }
            #pragma unroll
            for (int mi = 0; mi < 4; mi++)
                #pragma unroll
                for (int ni = 0; ni < 4; ni++)
                    mma_tf32(acc[mi][ni], af[mi][0], af[mi][1], af[mi][2], af[mi][3],
                             bf[ni][0], bf[ni][1]);
        }

        // store next tile into other buffer
        if (kt + 1 < NKT) {
            int nxt = cur ^ 1;
            #pragma unroll
            for (int i = 0; i < 4; i++) {
                int r = lrow + 32*i;
                int ch = lf ^ (r & 7);
                uint4 va = make_uint4(tf32r(pa[i].x), tf32r(pa[i].y), tf32r(pa[i].z), tf32r(pa[i].w));
                uint4 vb = make_uint4(tf32r(pb[i].x), tf32r(pb[i].y), tf32r(pb[i].z), tf32r(pb[i].w));
                *(uint4*)&As[nxt][r*32 + ch*4] = va;
                *(uint4*)&Bs[nxt][r*32 + ch*4] = vb;
            }
            __syncthreads();
        }
    }

    // epilogue: C fragment layout m16n8: (c0,c1) at row g8, cols 2*tq,2*tq+1;
    // (c2,c3) at row g8+8.
    #pragma unroll
    for (int mi = 0; mi < 4; mi++) {
        int gm0 = bM + wm + mi*16 + g8;
        int gm1 = gm0 + 8;
        #pragma unroll
        for (int ni = 0; ni < 4; ni++) {
            int gn = bN + wn + ni*8 + tq*2;
            float2 bs = *(const float2*)(bias + gn);
            if (gm0 < M) {
                float2 o0; o0.x = acc[mi][ni][0] + bs.x; o0.y = acc[mi][ni][1] + bs.y;
                *(float2*)(C + (size_t)gm0 * ldc + gn) = o0;
            }
            if (gm1 < M) {
                float2 o1; o1.x = acc[mi][ni][2] + bs.x; o1.y = acc[mi][ni][3] + bs.y;
                *(float2*)(C + (size_t)gm1 * ldc + gn) = o1;
            }
        }
    }
}

// ---------------------------------------------------------------------------
// Launch
// ---------------------------------------------------------------------------
extern "C" void kernel_launch(void* const* d_in, const int* in_sizes, int n_in,
                              void* d_out, int out_size) {
    const int*   tgt   = (const int*)  d_in[0];
    const float* enc   = (const float*)d_in[1];
    const float* act   = (const float*)d_in[2];
    const float* E     = (const float*)d_in[3];
    const float* Ww2h  = (const float*)d_in[4];
    const float* bw2h  = (const float*)d_in[5];
    const float* Wh2h  = (const float*)d_in[6];
    const float* bh2h  = (const float*)d_in[7];
    const float* Ww2hr = (const float*)d_in[8];
    const float* bw2hr = (const float*)d_in[9];
    const float* Wh2hr = (const float*)d_in[10];
    const float* bh2hr = (const float*)d_in[11];
    const float* Wdc   = (const float*)d_in[12];
    const float* Wout  = (const float*)d_in[13];
    const float* bout  = (const float*)d_in[14];
    float* out = (float*)d_out;

    float *pw4, *pwr, *phall;
    cudaGetSymbolAddress((void**)&pw4,   g_w4);
    cudaGetSymbolAddress((void**)&pwr,   g_wr);
    cudaGetSymbolAddress((void**)&phall, g_hall);

    // state init (h = enc, barrier counter = 0)
    init_kernel<<<(BB*DD + 255) / 256, 256>>>(enc);

    // precompute w4_all and wr_all (embedding gather fused into GEMM)
    {
        dim3 g1((G4 + TS - 1) / TS, (BB*TT + TS - 1) / TS);   // 16 x 14
        gemm_tn<true><<<g1, 256>>>(BB*TT, G4, DW, E, tgt, Ww2h, bw2h, pw4, G4);
        dim3 g2((AA + TS - 1) / TS, (BB*TT + TS - 1) / TS);   // 2 x 14
        gemm_tn<true><<<g2, 256>>>(BB*TT, AA, DW, E, tgt, Ww2hr, bw2hr, pwr, AA);
    }

    // whole recurrence in ONE persistent kernel
    recurrent_kernel<<<NB, NTHR>>>(Wh2h, bh2h, Wh2hr, bh2hr, Wdc, enc, act);

    // dominant output projection on tensor cores (tf32):
    // out[b*T+t, v] = h_all . W_out[v] + b_out[v]
    {
        dim3 g3(VV / 128, (BB*TT + 127) / 128);   // 250 x 14
        gemm_tf32<<<g3, 256>>>(BB*TT, DD, phall, Wout, bout, out, VV);
    }
}

// round 6
// speedup vs baseline: 1.9648x; 1.0835x over previous
#include <cuda_runtime.h>
#include <math.h>

// Problem constants
#define BATCH 32
#define TT 55
#define VV 32000
#define DW 256
#define DD 512
#define AA 200
#define G4 2048   // 4*D

#define NB   148   // persistent blocks
#define NTHR 256

// Scratch (device globals; no allocation allowed)
__device__ float    g_w4[BATCH*TT*G4];     // precomputed w4_all [b*T+t, 4D]
__device__ float    g_wr[BATCH*TT*AA];     // precomputed wr_all [b*T+t, A]
__device__ float    g_h[BATCH*DD];         // recurrent h state [B,D]
__device__ float    g_dt[BATCH*AA];        // dt state
__device__ float    g_gates[BATCH*G4];     // activated gates for current step
__device__ unsigned g_hall_tf[BATCH*TT*DD];// all h_t as tf32 bits, [b*T+t, D]
__device__ unsigned g_wout_tf[VV*DD];      // W_out pre-converted to tf32 bits
__device__ unsigned g_barcnt;              // grid barrier counter

// ---------------------------------------------------------------------------
__device__ __forceinline__ unsigned tf32r(float x) {
    unsigned y;
    asm("cvt.rna.tf32.f32 %0, %1;" : "=r"(y) : "f"(x));
    return y;
}

__global__ void init_kernel(const float* __restrict__ enc) {
    int i = blockIdx.x * blockDim.x + threadIdx.x;
    if (i < BATCH*DD) g_h[i] = enc[i];
    if (i == 0) g_barcnt = 0u;
}

// Convert W_out (fp32) -> tf32 bits, once per launch.
__global__ void __launch_bounds__(256) wout_convert(const float* __restrict__ W) {
    int i = blockIdx.x * blockDim.x + threadIdx.x;   // float4 index
    const float4 v = ((const float4*)W)[i];
    uint4 o = make_uint4(tf32r(v.x), tf32r(v.y), tf32r(v.z), tf32r(v.w));
    ((uint4*)g_wout_tf)[i] = o;
}

__device__ __forceinline__ float sigmoidf_(float x) {
    return 1.f / (1.f + expf(-x));
}

// Grid barrier
__device__ __forceinline__ void gridbar(unsigned tgt) {
    __syncthreads();
    if (threadIdx.x == 0) {
        __threadfence();
        atomicAdd(&g_barcnt, 1u);
        while (*((volatile unsigned*)&g_barcnt) < tgt) { }
        __threadfence();
    }
    __syncthreads();
}

// ---------------------------------------------------------------------------
// Persistent recurrence kernel (R4 structure; g_hall stored as tf32 bits).
// ---------------------------------------------------------------------------
__global__ void __launch_bounds__(NTHR, 1) recurrent_kernel(
    const float* __restrict__ Wh2h,  const float* __restrict__ bh2h,
    const float* __restrict__ Wh2hr, const float* __restrict__ bh2hr,
    const float* __restrict__ Wdc,
    const float* __restrict__ enc,   const float* __restrict__ act)
{
    __shared__ float hs[16 * DD];    // 32 KB

    const int blk  = blockIdx.x;
    const int tid  = threadIdx.x;
    const int w    = tid >> 5;
    const int lane = tid & 31;

    const int  task = blk;                 // valid if < 142
    const int  colg = task >> 1;
    const int  bh   = task & 1;
    const int  col  = colg * 32 + lane;
    const bool p1   = (task < 142) && (col < G4 + AA);
    const int  b0   = bh * 16 + w * 2;
    const int  b1   = b0 + 1;

    const float* Wrow = nullptr;
    float bias = 0.f;
    bool  is_r = false;
    int   acol = 0;
    if (p1) {
        if (col < G4) { Wrow = Wh2h + (size_t)col * DD; bias = bh2h[col]; }
        else { is_r = true; acol = col - G4;
               Wrow = Wh2hr + (size_t)acol * DD; bias = bh2hr[acol]; }
    }
    float d0 = 0.f, d1 = 0.f;
    if (p1 && is_r) {
        d0 = __ldcg(act + b0 * AA + acol);
        d1 = __ldcg(act + b1 * AA + acol);
    }

    const bool p2 = (blk < 64);
    const int  colg2 = blk >> 2;
    const int  b2    = (blk & 3) * 8 + w;
    const int  j2    = colg2 * 32 + lane;
    const float* WdcRow = Wdc + (size_t)j2 * AA;
    float creg = 0.f;
    if (p2) creg = __ldcg(enc + b2 * DD + j2);

    unsigned tgt = NB;

    for (int t = 0; t < TT; t++) {
        if (task < 142) {
            const float4* src = (const float4*)(g_h + bh * 16 * DD);
            float4* dst = (float4*)hs;
            #pragma unroll
            for (int i = 0; i < (16 * DD / 4) / NTHR; i++)
                dst[i * NTHR + tid] = __ldcg(src + i * NTHR + tid);
        }
        __syncthreads();

        if (p1) {
            const float4* h0 = (const float4*)(hs + (w * 2)     * DD);
            const float4* h1 = (const float4*)(hs + (w * 2 + 1) * DD);
            const float4* wp = (const float4*)Wrow;
            float acc0 = 0.f, acc1 = 0.f;
            #pragma unroll 8
            for (int k = 0; k < DD / 4; k++) {
                float4 wv = wp[k];
                float4 a  = h0[k];
                float4 b  = h1[k];
                acc0 += wv.x*a.x + wv.y*a.y + wv.z*a.z + wv.w*a.w;
                acc1 += wv.x*b.x + wv.y*b.y + wv.z*b.z + wv.w*b.w;
            }
            if (!is_r) {
                float v0 = g_w4[(size_t)(b0*TT + t) * G4 + col] + acc0 + bias;
                float v1 = g_w4[(size_t)(b1*TT + t) * G4 + col] + acc1 + bias;
                v0 = (col < 3*DD) ? sigmoidf_(v0) : tanhf(v0);
                v1 = (col < 3*DD) ? sigmoidf_(v1) : tanhf(v1);
                g_gates[b0 * G4 + col] = v0;
                g_gates[b1 * G4 + col] = v1;
            } else {
                float r0 = sigmoidf_(g_wr[(size_t)(b0*TT + t) * AA + acol] + acc0 + bias);
                float r1 = sigmoidf_(g_wr[(size_t)(b1*TT + t) * AA + acol] + acc1 + bias);
                d0 *= r0;
                d1 *= r1;
                g_dt[b0 * AA + acol] = d0;
                g_dt[b1 * AA + acol] = d1;
            }
        }

        gridbar(tgt); tgt += NB;

        if (p2) {
            const float4* dtp = (const float4*)(g_dt + b2 * AA);
            const float4* wp  = (const float4*)WdcRow;
            float acc = 0.f;
            #pragma unroll
            for (int k = 0; k < AA / 4; k++) {
                float4 dv = __ldcg(dtp + k);
                float4 wv = wp[k];
                acc += wv.x*dv.x + wv.y*dv.y + wv.z*dv.z + wv.w*dv.w;
            }
            float dtw = tanhf(acc);
            float gi = __ldcg(g_gates + b2 * G4 + j2);
            float gf = __ldcg(g_gates + b2 * G4 + DD   + j2);
            float go = __ldcg(g_gates + b2 * G4 + 2*DD + j2);
            float ch = __ldcg(g_gates + b2 * G4 + 3*DD + j2);
            creg = gf * creg + gi * ch + dtw;
            float h = go * tanhf(creg);
            g_h[b2 * DD + j2] = h;
            g_hall_tf[(size_t)(b2 * TT + t) * DD + j2] = tf32r(h);
        }

        gridbar(tgt); tgt += NB;
    }
}

// ---------------------------------------------------------------------------
// fp32 tiled GEMM (kept for the two small precompute GEMMs)
// ---------------------------------------------------------------------------
#define TS 128
#define KT 8

template<bool GATHER>
__global__ void __launch_bounds__(256) gemm_tn(
    int M, int N, int K,
    const float* __restrict__ A, const int* __restrict__ idx,
    const float* __restrict__ B,
    const float* __restrict__ bias,
    float* __restrict__ C, int ldc)
{
    __shared__ float As[KT][TS];
    __shared__ float Bs[KT][TS];

    int tid = threadIdx.x;
    int lrow = tid >> 1;
    int kc   = (tid & 1) * 4;

    int gm_l = blockIdx.y * TS + lrow;
    int gn_l = blockIdx.x * TS + lrow;

    const float* aptr = nullptr;
    if (gm_l < M) {
        int ar = GATHER ? idx[gm_l] : gm_l;
        aptr = A + (size_t)ar * K;
    }
    const float* bptr = (gn_l < N) ? (B + (size_t)gn_l * K) : nullptr;

    int tx = tid & 15;
    int ty = tid >> 4;

    float acc[8][8];
    #pragma unroll
    for (int i = 0; i < 8; i++)
        #pragma unroll
        for (int j = 0; j < 8; j++) acc[i][j] = 0.f;

    for (int k0 = 0; k0 < K; k0 += KT) {
        float4 av = make_float4(0.f, 0.f, 0.f, 0.f);
        float4 bv = make_float4(0.f, 0.f, 0.f, 0.f);
        if (aptr) av = *(const float4*)(aptr + k0 + kc);
        if (bptr) bv = *(const float4*)(bptr + k0 + kc);
        __syncthreads();
        As[kc+0][lrow] = av.x; As[kc+1][lrow] = av.y;
        As[kc+2][lrow] = av.z; As[kc+3][lrow] = av.w;
        Bs[kc+0][lrow] = bv.x; Bs[kc+1][lrow] = bv.y;
        Bs[kc+2][lrow] = bv.z; Bs[kc+3][lrow] = bv.w;
        __syncthreads();
        #pragma unroll
        for (int kk = 0; kk < KT; kk++) {
            float4 a0 = *(const float4*)&As[kk][ty*8];
            float4 a1 = *(const float4*)&As[kk][ty*8+4];
            float4 b0 = *(const float4*)&Bs[kk][tx*8];
            float4 b1 = *(const float4*)&Bs[kk][tx*8+4];
            float a[8] = {a0.x,a0.y,a0.z,a0.w,a1.x,a1.y,a1.z,a1.w};
            float b[8] = {b0.x,b0.y,b0.z,b0.w,b1.x,b1.y,b1.z,b1.w};
            #pragma unroll
            for (int i = 0; i < 8; i++)
                #pragma unroll
                for (int j = 0; j < 8; j++)
                    acc[i][j] += a[i] * b[j];
        }
    }

    #pragma unroll
    for (int i = 0; i < 8; i++) {
        int gm = blockIdx.y * TS + ty*8 + i;
        if (gm < M) {
            #pragma unroll
            for (int j = 0; j < 8; j += 4) {
                int gn = blockIdx.x * TS + tx*8 + j;
                if (gn < N) {
                    float4 bs = *(const float4*)(bias + gn);
                    float4 o;
                    o.x = acc[i][j+0] + bs.x;
                    o.y = acc[i][j+1] + bs.y;
                    o.z = acc[i][j+2] + bs.z;
                    o.w = acc[i][j+3] + bs.w;
                    *(float4*)(C + (size_t)gm * ldc + gn) = o;
                }
            }
        }
    }
}

// ---------------------------------------------------------------------------
// tf32 tensor-core GEMM v2: C[M,N] = A[M,K] @ B[N,K]^T + bias[N]
// Operands pre-converted to tf32 bits. CTA tile 128x256, K-tile 32,
// 8 warps (warp tile 64x64), 3-stage cp.async pipeline, XOR-swizzled smem.
// Requires N % 256 == 0, K % 32 == 0 (N=32000, K=512: ok).
// ---------------------------------------------------------------------------
#define BM 128
#define BN 256
#define BK 32
#define NSTAGE 3
// smem: A stage = 128*32 uints (16KB), B stage = 256*32 uints (32KB)
#define A_STAGE (BM*BK)
#define B_STAGE (BN*BK)
#define SMEM_UINTS (NSTAGE*(A_STAGE+B_STAGE))   // 36864 uints = 144KB

__device__ __forceinline__ void mma_tf32(float c[4],
    unsigned a0, unsigned a1, unsigned a2, unsigned a3,
    unsigned b0, unsigned b1)
{
    asm volatile(
        "mma.sync.aligned.m16n8k8.row.col.f32.tf32.tf32.f32 "
        "{%0,%1,%2,%3}, {%4,%5,%6,%7}, {%8,%9}, {%0,%1,%2,%3};\n"
        : "+f"(c[0]), "+f"(c[1]), "+f"(c[2]), "+f"(c[3])
        : "r"(a0), "r"(a1), "r"(a2), "r"(a3), "r"(b0), "r"(b1));
}

__device__ __forceinline__ void cpasync16(unsigned saddr, const void* gptr) {
    asm volatile("cp.async.cg.shared.global [%0], [%1], 16;"
                 :: "r"(saddr), "l"(gptr));
}

__global__ void __launch_bounds__(256, 1) gemm_tf32_v2(
    int M,
    const unsigned* __restrict__ A,   // [M,K] tf32 bits (K=DD)
    const unsigned* __restrict__ B,   // [N,K] tf32 bits
    const float* __restrict__ bias,
    float* __restrict__ C, int ldc)
{
    extern __shared__ unsigned smem_u[];

    const int tid  = threadIdx.x;
    const int lane = tid & 31;
    const int w    = tid >> 5;
    const int wm   = (w & 1) * 64;       // warp m offset
    const int wn   = (w >> 1) * 64;      // warp n offset
    const int g8   = lane >> 2;
    const int tq   = lane & 3;

    const int bM = blockIdx.y * BM;
    const int bN = blockIdx.x * BN;

    // loader mapping: chunk f = tid&7 (16B chunks within 128B row),
    // base row = tid>>3; A: 4 rows strided 32; B: 8 rows strided 32
    const int lf   = tid & 7;
    const int lrow = tid >> 3;

    const unsigned smem_base =
        (unsigned)__cvta_generic_to_shared(smem_u);

    float acc[4][8][4];
    #pragma unroll
    for (int mi = 0; mi < 4; mi++)
        #pragma unroll
        for (int ni = 0; ni < 8; ni++)
            #pragma unroll
            for (int q = 0; q < 4; q++) acc[mi][ni][q] = 0.f;

    const int NKT = DD / BK;   // 16

    // tile loader: stage st <- k-tile kt
    auto load_tile = [&](int st, int kt) {
        const unsigned aoff = smem_base + (st * A_STAGE) * 4u;
        const unsigned boff = smem_base + (NSTAGE * A_STAGE + st * B_STAGE) * 4u;
        #pragma unroll
        for (int i = 0; i < 4; i++) {
            int r = lrow + 32*i;
            int gr = bM + r; if (gr >= M) gr = M - 1;
            int ch = lf ^ (r & 7);
            cpasync16(aoff + (r*BK + ch*4) * 4u,
                      A + (size_t)gr * DD + (size_t)kt*BK + lf*4);
        }
        #pragma unroll
        for (int i = 0; i < 8; i++) {
            int r = lrow + 32*i;
            int gn = bN + r;
            int ch = lf ^ (r & 7);
            cpasync16(boff + (r*BK + ch*4) * 4u,
                      B + (size_t)gn * DD + (size_t)kt*BK + lf*4);
        }
    };

    // preload stages 0..2
    #pragma unroll
    for (int st = 0; st < NSTAGE; st++) {
        load_tile(st, st);
        asm volatile("cp.async.commit_group;");
    }

    for (int kt = 0; kt < NKT; kt++) {
        asm volatile("cp.async.wait_group %0;" :: "n"(NSTAGE - 1));
        __syncthreads();

        const int st = kt % NSTAGE;
        const unsigned* sA = smem_u + st * A_STAGE;
        const unsigned* sB = smem_u + NSTAGE * A_STAGE + st * B_STAGE;

        #pragma unroll
        for (int s = 0; s < 4; s++) {
            const int c0 = s*2;
            const int c1 = s*2 + 1;
            unsigned af[4][4];
            #pragma unroll
            for (int mi = 0; mi < 4; mi++) {
                int r0 = wm + mi*16 + g8;
                int r1 = r0 + 8;
                af[mi][0] = sA[r0*BK + ((c0 ^ (r0 & 7))*4 + tq)];
                af[mi][1] = sA[r1*BK + ((c0 ^ (r1 & 7))*4 + tq)];
                af[mi][2] = sA[r0*BK + ((c1 ^ (r0 & 7))*4 + tq)];
                af[mi][3] = sA[r1*BK + ((c1 ^ (r1 & 7))*4 + tq)];
            }
            unsigned bf[8][2];
            #pragma unroll
            for (int ni = 0; ni < 8; ni++) {
                int n0 = wn + ni*8 + g8;
                bf[ni][0] = sB[n0*BK + ((c0 ^ (n0 & 7))*4 + tq)];
                bf[ni][1] = sB[n0*BK + ((c1 ^ (n0 & 7))*4 + tq)];
            }
            #pragma unroll
            for (int mi = 0; mi < 4; mi++)
                #pragma unroll
                for (int ni = 0; ni < 8; ni++)
                    mma_tf32(acc[mi][ni], af[mi][0], af[mi][1], af[mi][2],
                             af[mi][3], bf[ni][0], bf[ni][1]);
        }

        __syncthreads();   // all warps done with stage st before overwrite
        if (kt + NSTAGE < NKT) load_tile(st, kt + NSTAGE);
        asm volatile("cp.async.commit_group;");   // (possibly empty group)
    }

    // epilogue
    #pragma unroll
    for (int mi = 0; mi < 4; mi++) {
        int gm0 = bM + wm + mi*16 + g8;
        int gm1 = gm0 + 8;
        #pragma unroll
        for (int ni = 0; ni < 8; ni++) {
            int gn = bN + wn + ni*8 + tq*2;
            float2 bs = *(const float2*)(bias + gn);
            if (gm0 < M) {
                float2 o0; o0.x = acc[mi][ni][0] + bs.x; o0.y = acc[mi][ni][1] + bs.y;
                *(float2*)(C + (size_t)gm0 * ldc + gn) = o0;
            }
            if (gm1 < M) {
                float2 o1; o1.x = acc[mi][ni][2] + bs.x; o1.y = acc[mi][ni][3] + bs.y;
                *(float2*)(C + (size_t)gm1 * ldc + gn) = o1;
            }
        }
    }
}

// ---------------------------------------------------------------------------
// Launch
// ---------------------------------------------------------------------------
extern "C" void kernel_launch(void* const* d_in, const int* in_sizes, int n_in,
                              void* d_out, int out_size) {
    const int*   tgt   = (const int*)  d_in[0];
    const float* enc   = (const float*)d_in[1];
    const float* act   = (const float*)d_in[2];
    const float* E     = (const float*)d_in[3];
    const float* Ww2h  = (const float*)d_in[4];
    const float* bw2h  = (const float*)d_in[5];
    const float* Wh2h  = (const float*)d_in[6];
    const float* bh2h  = (const float*)d_in[7];
    const float* Ww2hr = (const float*)d_in[8];
    const float* bw2hr = (const float*)d_in[9];
    const float* Wh2hr = (const float*)d_in[10];
    const float* bh2hr = (const float*)d_in[11];
    const float* Wdc   = (const float*)d_in[12];
    const float* Wout  = (const float*)d_in[13];
    const float* bout  = (const float*)d_in[14];
    float* out = (float*)d_out;

    float *pw4, *pwr;
    unsigned *phall, *pwout;
    cudaGetSymbolAddress((void**)&pw4,   g_w4);
    cudaGetSymbolAddress((void**)&pwr,   g_wr);
    cudaGetSymbolAddress((void**)&phall, g_hall_tf);
    cudaGetSymbolAddress((void**)&pwout, g_wout_tf);

    static bool attr_done = false;
    if (!attr_done) {
        cudaFuncSetAttribute(gemm_tf32_v2,
                             cudaFuncAttributeMaxDynamicSharedMemorySize,
                             SMEM_UINTS * 4);
        attr_done = true;
    }

    // state init (h = enc, barrier counter = 0)
    init_kernel<<<(BATCH*DD + 255) / 256, 256>>>(enc);

    // pre-convert W_out to tf32 bits (no recurrence dependency)
    wout_convert<<<(VV*DD/4 + 255) / 256, 256>>>(Wout);

    // precompute w4_all and wr_all (embedding gather fused into GEMM)
    {
        dim3 g1((G4 + TS - 1) / TS, (BATCH*TT + TS - 1) / TS);
        gemm_tn<true><<<g1, 256>>>(BATCH*TT, G4, DW, E, tgt, Ww2h, bw2h, pw4, G4);
        dim3 g2((AA + TS - 1) / TS, (BATCH*TT + TS - 1) / TS);
        gemm_tn<true><<<g2, 256>>>(BATCH*TT, AA, DW, E, tgt, Ww2hr, bw2hr, pwr, AA);
    }

    // whole recurrence in ONE persistent kernel
    recurrent_kernel<<<NB, NTHR>>>(Wh2h, bh2h, Wh2hr, bh2hr, Wdc, enc, act);

    // dominant output projection on tensor cores (tf32, pre-converted)
    {
        dim3 g3(VV / BN, (BATCH*TT + BM - 1) / BM);   // 125 x 14
        gemm_tf32_v2<<<g3, 256, SMEM_UINTS * 4>>>(BATCH*TT, phall, pwout,
                                                  bout, out, VV);
    }
}

// round 8
// speedup vs baseline: 1.9995x; 1.0176x over previous
#include <cuda_runtime.h>
#include <math.h>

// Problem constants
#define BATCH 32
#define TT 55
#define VV 32000
#define DW 256
#define DD 512
#define AA 200
#define G4 2048   // 4*D

#define NBLK 142   // persistent blocks (all co-resident; 142 <= 148 SMs)
#define NTHR 256

// Scratch (device globals; no allocation allowed)
__device__ float    g_w4[BATCH*TT*G4];     // precomputed w4_all [b*T+t, 4D]
__device__ float    g_wr[BATCH*TT*AA];     // precomputed wr_all [b*T+t, A]
__device__ float    g_h[BATCH*DD];         // recurrent h state [B,D]
__device__ float    g_dt[BATCH*AA];        // dt state
__device__ float    g_gates[BATCH*G4];     // activated gates for current step
__device__ unsigned g_hall_tf[BATCH*TT*DD];// all h_t as tf32 bits, [b*T+t, D]
__device__ unsigned g_wout_tf[VV*DD];      // W_out pre-converted to tf32 bits
__device__ unsigned g_arrA;                // phase1-done arrivals (monotonic)
__device__ unsigned g_arrB;                // phase2-done arrivals (monotonic)

// ---------------------------------------------------------------------------
__device__ __forceinline__ unsigned tf32r(float x) {
    unsigned y;
    asm("cvt.rna.tf32.f32 %0, %1;" : "=r"(y) : "f"(x));
    return y;
}

__global__ void init_kernel(const float* __restrict__ enc) {
    int i = blockIdx.x * blockDim.x + threadIdx.x;
    if (i < BATCH*DD) g_h[i] = enc[i];
    if (i == 0) { g_arrA = 0u; g_arrB = 0u; }
}

// Convert W_out (fp32) -> tf32 bits, once per launch.
__global__ void __launch_bounds__(256) wout_convert(const float* __restrict__ W) {
    int i = blockIdx.x * blockDim.x + threadIdx.x;   // float4 index
    const float4 v = ((const float4*)W)[i];
    uint4 o = make_uint4(tf32r(v.x), tf32r(v.y), tf32r(v.z), tf32r(v.w));
    ((uint4*)g_wout_tf)[i] = o;
}

__device__ __forceinline__ float sigmoidf_(float x) {
    return 1.f / (1.f + expf(-x));
}

// Fence-free semaphores. release-red orders all CTA threads' prior stores
// (via the bar.sync happens-before chain); acquire-poll orders subsequent
// loads. NO CCTL.IVALL is emitted -> L1D (weights) stays resident.
// All mutable cross-CTA data is read via __ldcg (L2), so no L1 staleness.
__device__ __forceinline__ void sem_arrive(unsigned* ctr) {
    __syncthreads();
    if (threadIdx.x == 0)
        asm volatile("red.release.gpu.global.add.u32 [%0], 1;"
                     :: "l"(ctr) : "memory");
}
__device__ __forceinline__ void sem_wait(unsigned* ctr, unsigned tgt) {
    if (threadIdx.x == 0) {
        unsigned v;
        do {
            asm volatile("ld.acquire.gpu.global.u32 %0, [%1];"
                         : "=r"(v) : "l"(ctr) : "memory");
        } while (v < tgt);
    }
    __syncthreads();
}

// ---------------------------------------------------------------------------
// Persistent recurrence kernel.
// Phase1: 142 blocks; block=(colgroup,batch-half); warp lane=col, 2 batches.
// Phase2: blocks 0..63; dtw=tanh(dt@Wdc^T), cell update, h store (tf32 too).
// Sync: phase1 blocks arrive A, wait only on B; phase2 blocks wait A, arrive B.
// ---------------------------------------------------------------------------
__global__ void __launch_bounds__(NTHR, 1) recurrent_kernel(
    const float* __restrict__ Wh2h,  const float* __restrict__ bh2h,
    const float* __restrict__ Wh2hr, const float* __restrict__ bh2hr,
    const float* __restrict__ Wdc,
    const float* __restrict__ enc,   const float* __restrict__ act)
{
    __shared__ float hs[16 * DD];    // 32 KB

    const int blk  = blockIdx.x;
    const int tid  = threadIdx.x;
    const int w    = tid >> 5;
    const int lane = tid & 31;

    const int  colg = blk >> 1;
    const int  bh   = blk & 1;
    const int  col  = colg * 32 + lane;
    const bool p1   = (col < G4 + AA);
    const int  b0   = bh * 16 + w * 2;
    const int  b1   = b0 + 1;

    const float* Wrow = nullptr;
    float bias = 0.f;
    bool  is_r = false;
    int   acol = 0;
    if (p1) {
        if (col < G4) { Wrow = Wh2h + (size_t)col * DD; bias = bh2h[col]; }
        else { is_r = true; acol = col - G4;
               Wrow = Wh2hr + (size_t)acol * DD; bias = bh2hr[acol]; }
    }
    float d0 = 0.f, d1 = 0.f;
    if (p1 && is_r) {
        d0 = __ldcg(act + b0 * AA + acol);
        d1 = __ldcg(act + b1 * AA + acol);
    }

    const bool p2 = (blk < 64);
    const int  colg2 = blk >> 2;
    const int  b2    = (blk & 3) * 8 + w;
    const int  j2    = colg2 * 32 + lane;
    const float* WdcRow = Wdc + (size_t)j2 * AA;
    float creg = 0.f;
    if (p2) creg = __ldcg(enc + b2 * DD + j2);

    unsigned* arrA; unsigned* arrB;
    asm("cvta.global.u64 %0, g_arrA;" : "=l"(arrA));
    asm("cvta.global.u64 %0, g_arrB;" : "=l"(arrB));

    for (int t = 0; t < TT; t++) {
        // ---- wait until h(t) is ready (phase2 of step t-1) ----
        sem_wait(arrB, 64u * (unsigned)t);

        // ---- stage h[bh*16 ..][:] into smem (L2 via .cg) ----
        {
            const float4* src = (const float4*)(g_h + bh * 16 * DD);
            float4* dst = (float4*)hs;
            #pragma unroll
            for (int i = 0; i < (16 * DD / 4) / NTHR; i++)
                dst[i * NTHR + tid] = __ldcg(src + i * NTHR + tid);
        }
        __syncthreads();

        // ---- phase1 compute (weights stay L1-resident: no fence flush) ----
        if (p1) {
            const float4* h0 = (const float4*)(hs + (w * 2)     * DD);
            const float4* h1 = (const float4*)(hs + (w * 2 + 1) * DD);
            const float4* wp = (const float4*)Wrow;
            float acc0 = 0.f, acc1 = 0.f;
            #pragma unroll 8
            for (int k = 0; k < DD / 4; k++) {
                float4 wv = wp[k];
                float4 a  = h0[k];
                float4 b  = h1[k];
                acc0 += wv.x*a.x + wv.y*a.y + wv.z*a.z + wv.w*a.w;
                acc1 += wv.x*b.x + wv.y*b.y + wv.z*b.z + wv.w*b.w;
            }
            if (!is_r) {
                float v0 = g_w4[(size_t)(b0*TT + t) * G4 + col] + acc0 + bias;
                float v1 = g_w4[(size_t)(b1*TT + t) * G4 + col] + acc1 + bias;
                v0 = (col < 3*DD) ? sigmoidf_(v0) : tanhf(v0);
                v1 = (col < 3*DD) ? sigmoidf_(v1) : tanhf(v1);
                g_gates[b0 * G4 + col] = v0;
                g_gates[b1 * G4 + col] = v1;
            } else {
                float r0 = sigmoidf_(g_wr[(size_t)(b0*TT + t) * AA + acol] + acc0 + bias);
                float r1 = sigmoidf_(g_wr[(size_t)(b1*TT + t) * AA + acol] + acc1 + bias);
                d0 *= r0;
                d1 *= r1;
                g_dt[b0 * AA + acol] = d0;
                g_dt[b1 * AA + acol] = d1;
            }
        }

        // ---- announce phase1 done (release) ----
        sem_arrive(arrA);

        // ---- phase2 on blocks 0..63 only ----
        if (p2) {
            sem_wait(arrA, 142u * (unsigned)(t + 1));

            const float4* dtp = (const float4*)(g_dt + b2 * AA);
            const float4* wp  = (const float4*)WdcRow;
            float acc = 0.f;
            #pragma unroll
            for (int k = 0; k < AA / 4; k++) {
                float4 dv = __ldcg(dtp + k);
                float4 wv = wp[k];
                acc += wv.x*dv.x + wv.y*dv.y + wv.z*dv.z + wv.w*dv.w;
            }
            float dtw = tanhf(acc);
            float gi = __ldcg(g_gates + b2 * G4 + j2);
            float gf = __ldcg(g_gates + b2 * G4 + DD   + j2);
            float go = __ldcg(g_gates + b2 * G4 + 2*DD + j2);
            float ch = __ldcg(g_gates + b2 * G4 + 3*DD + j2);
            creg = gf * creg + gi * ch + dtw;
            float h = go * tanhf(creg);
            g_h[b2 * DD + j2] = h;
            g_hall_tf[(size_t)(b2 * TT + t) * DD + j2] = tf32r(h);

            sem_arrive(arrB);
        }
    }
}

// ---------------------------------------------------------------------------
// fp32 tiled GEMM (two small precompute GEMMs)
// ---------------------------------------------------------------------------
#define TS 128
#define KT 8

template<bool GATHER>
__global__ void __launch_bounds__(256) gemm_tn(
    int M, int N, int K,
    const float* __restrict__ A, const int* __restrict__ idx,
    const float* __restrict__ B,
    const float* __restrict__ bias,
    float* __restrict__ C, int ldc)
{
    __shared__ float As[KT][TS];
    __shared__ float Bs[KT][TS];

    int tid = threadIdx.x;
    int lrow = tid >> 1;
    int kc   = (tid & 1) * 4;

    int gm_l = blockIdx.y * TS + lrow;
    int gn_l = blockIdx.x * TS + lrow;

    const float* aptr = nullptr;
    if (gm_l < M) {
        int ar = GATHER ? idx[gm_l] : gm_l;
        aptr = A + (size_t)ar * K;
    }
    const float* bptr = (gn_l < N) ? (B + (size_t)gn_l * K) : nullptr;

    int tx = tid & 15;
    int ty = tid >> 4;

    float acc[8][8];
    #pragma unroll
    for (int i = 0; i < 8; i++)
        #pragma unroll
        for (int j = 0; j < 8; j++) acc[i][j] = 0.f;

    for (int k0 = 0; k0 < K; k0 += KT) {
        float4 av = make_float4(0.f, 0.f, 0.f, 0.f);
        float4 bv = make_float4(0.f, 0.f, 0.f, 0.f);
        if (aptr) av = *(const float4*)(aptr + k0 + kc);
        if (bptr) bv = *(const float4*)(bptr + k0 + kc);
        __syncthreads();
        As[kc+0][lrow] = av.x; As[kc+1][lrow] = av.y;
        As[kc+2][lrow] = av.z; As[kc+3][lrow] = av.w;
        Bs[kc+0][lrow] = bv.x; Bs[kc+1][lrow] = bv.y;
        Bs[kc+2][lrow] = bv.z; Bs[kc+3][lrow] = bv.w;
        __syncthreads();
        #pragma unroll
        for (int kk = 0; kk < KT; kk++) {
            float4 a0 = *(const float4*)&As[kk][ty*8];
            float4 a1 = *(const float4*)&As[kk][ty*8+4];
            float4 b0 = *(const float4*)&Bs[kk][tx*8];
            float4 b1 = *(const float4*)&Bs[kk][tx*8+4];
            float a[8] = {a0.x,a0.y,a0.z,a0.w,a1.x,a1.y,a1.z,a1.w};
            float b[8] = {b0.x,b0.y,b0.z,b0.w,b1.x,b1.y,b1.z,b1.w};
            #pragma unroll
            for (int i = 0; i < 8; i++)
                #pragma unroll
                for (int j = 0; j < 8; j++)
                    acc[i][j] += a[i] * b[j];
        }
    }

    #pragma unroll
    for (int i = 0; i < 8; i++) {
        int gm = blockIdx.y * TS + ty*8 + i;
        if (gm < M) {
            #pragma unroll
            for (int j = 0; j < 8; j += 4) {
                int gn = blockIdx.x * TS + tx*8 + j;
                if (gn < N) {
                    float4 bs = *(const float4*)(bias + gn);
                    float4 o;
                    o.x = acc[i][j+0] + bs.x;
                    o.y = acc[i][j+1] + bs.y;
                    o.z = acc[i][j+2] + bs.z;
                    o.w = acc[i][j+3] + bs.w;
                    *(float4*)(C + (size_t)gm * ldc + gn) = o;
                }
            }
        }
    }
}

// ---------------------------------------------------------------------------
// tf32 tensor-core GEMM v2 (unchanged from R6 — measured win)
// ---------------------------------------------------------------------------
#define BM 128
#define BN 256
#define BK 32
#define NSTAGE 3
#define A_STAGE (BM*BK)
#define B_STAGE (BN*BK)
#define SMEM_UINTS (NSTAGE*(A_STAGE+B_STAGE))   // 144KB

__device__ __forceinline__ void mma_tf32(float c[4],
    unsigned a0, unsigned a1, unsigned a2, unsigned a3,
    unsigned b0, unsigned b1)
{
    asm volatile(
        "mma.sync.aligned.m16n8k8.row.col.f32.tf32.tf32.f32 "
        "{%0,%1,%2,%3}, {%4,%5,%6,%7}, {%8,%9}, {%0,%1,%2,%3};\n"
        : "+f"(c[0]), "+f"(c[1]), "+f"(c[2]), "+f"(c[3])
        : "r"(a0), "r"(a1), "r"(a2), "r"(a3), "r"(b0), "r"(b1));
}

__device__ __forceinline__ void cpasync16(unsigned saddr, const void* gptr) {
    asm volatile("cp.async.cg.shared.global [%0], [%1], 16;"
                 :: "r"(saddr), "l"(gptr));
}

__global__ void __launch_bounds__(256, 1) gemm_tf32_v2(
    int M,
    const unsigned* __restrict__ A,   // [M,K] tf32 bits (K=DD)
    const unsigned* __restrict__ B,   // [N,K] tf32 bits
    const float* __restrict__ bias,
    float* __restrict__ C, int ldc)
{
    extern __shared__ unsigned smem_u[];

    const int tid  = threadIdx.x;
    const int lane = tid & 31;
    const int w    = tid >> 5;
    const int wm   = (w & 1) * 64;
    const int wn   = (w >> 1) * 64;
    const int g8   = lane >> 2;
    const int tq   = lane & 3;

    const int bM = blockIdx.y * BM;
    const int bN = blockIdx.x * BN;

    const int lf   = tid & 7;
    const int lrow = tid >> 3;

    const unsigned smem_base = (unsigned)__cvta_generic_to_shared(smem_u);

    float acc[4][8][4];
    #pragma unroll
    for (int mi = 0; mi < 4; mi++)
        #pragma unroll
        for (int ni = 0; ni < 8; ni++)
            #pragma unroll
            for (int q = 0; q < 4; q++) acc[mi][ni][q] = 0.f;

    const int NKT = DD / BK;   // 16

    auto load_tile = [&](int st, int kt) {
        const unsigned aoff = smem_base + (st * A_STAGE) * 4u;
        const unsigned boff = smem_base + (NSTAGE * A_STAGE + st * B_STAGE) * 4u;
        #pragma unroll
        for (int i = 0; i < 4; i++) {
            int r = lrow + 32*i;
            int gr = bM + r; if (gr >= M) gr = M - 1;
            int ch = lf ^ (r & 7);
            cpasync16(aoff + (r*BK + ch*4) * 4u,
                      A + (size_t)gr * DD + (size_t)kt*BK + lf*4);
        }
        #pragma unroll
        for (int i = 0; i < 8; i++) {
            int r = lrow + 32*i;
            int gn = bN + r;
            int ch = lf ^ (r & 7);
            cpasync16(boff + (r*BK + ch*4) * 4u,
                      B + (size_t)gn * DD + (size_t)kt*BK + lf*4);
        }
    };

    #pragma unroll
    for (int st = 0; st < NSTAGE; st++) {
        load_tile(st, st);
        asm volatile("cp.async.commit_group;");
    }

    for (int kt = 0; kt < NKT; kt++) {
        asm volatile("cp.async.wait_group %0;" :: "n"(NSTAGE - 1));
        __syncthreads();

        const int st = kt % NSTAGE;
        const unsigned* sA = smem_u + st * A_STAGE;
        const unsigned* sB = smem_u + NSTAGE * A_STAGE + st * B_STAGE;

        #pragma unroll
        for (int s = 0; s < 4; s++) {
            const int c0 = s*2;
            const int c1 = s*2 + 1;
            unsigned af[4][4];
            #pragma unroll
            for (int mi = 0; mi < 4; mi++) {
                int r0 = wm + mi*16 + g8;
                int r1 = r0 + 8;
                af[mi][0] = sA[r0*BK + ((c0 ^ (r0 & 7))*4 + tq)];
                af[mi][1] = sA[r1*BK + ((c0 ^ (r1 & 7))*4 + tq)];
                af[mi][2] = sA[r0*BK + ((c1 ^ (r0 & 7))*4 + tq)];
                af[mi][3] = sA[r1*BK + ((c1 ^ (r1 & 7))*4 + tq)];
            }
            unsigned bf[8][2];
            #pragma unroll
            for (int ni = 0; ni < 8; ni++) {
                int n0 = wn + ni*8 + g8;
                bf[ni][0] = sB[n0*BK + ((c0 ^ (n0 & 7))*4 + tq)];
                bf[ni][1] = sB[n0*BK + ((c1 ^ (n0 & 7))*4 + tq)];
            }
            #pragma unroll
            for (int mi = 0; mi < 4; mi++)
                #pragma unroll
                for (int ni = 0; ni < 8; ni++)
                    mma_tf32(acc[mi][ni], af[mi][0], af[mi][1], af[mi][2],
                             af[mi][3], bf[ni][0], bf[ni][1]);
        }

        __syncthreads();
        if (kt + NSTAGE < NKT) load_tile(st, kt + NSTAGE);
        asm volatile("cp.async.commit_group;");
    }

    #pragma unroll
    for (int mi = 0; mi < 4; mi++) {
        int gm0 = bM + wm + mi*16 + g8;
        int gm1 = gm0 + 8;
        #pragma unroll
        for (int ni = 0; ni < 8; ni++) {
            int gn = bN + wn + ni*8 + tq*2;
            float2 bs = *(const float2*)(bias + gn);
            if (gm0 < M) {
                float2 o0; o0.x = acc[mi][ni][0] + bs.x; o0.y = acc[mi][ni][1] + bs.y;
                *(float2*)(C + (size_t)gm0 * ldc + gn) = o0;
            }
            if (gm1 < M) {
                float2 o1; o1.x = acc[mi][ni][2] + bs.x; o1.y = acc[mi][ni][3] + bs.y;
                *(float2*)(C + (size_t)gm1 * ldc + gn) = o1;
            }
        }
    }
}

// ---------------------------------------------------------------------------
// Launch
// ---------------------------------------------------------------------------
extern "C" void kernel_launch(void* const* d_in, const int* in_sizes, int n_in,
                              void* d_out, int out_size) {
    const int*   tgt   = (const int*)  d_in[0];
    const float* enc   = (const float*)d_in[1];
    const float* act   = (const float*)d_in[2];
    const float* E     = (const float*)d_in[3];
    const float* Ww2h  = (const float*)d_in[4];
    const float* bw2h  = (const float*)d_in[5];
    const float* Wh2h  = (const float*)d_in[6];
    const float* bh2h  = (const float*)d_in[7];
    const float* Ww2hr = (const float*)d_in[8];
    const float* bw2hr = (const float*)d_in[9];
    const float* Wh2hr = (const float*)d_in[10];
    const float* bh2hr = (const float*)d_in[11];
    const float* Wdc   = (const float*)d_in[12];
    const float* Wout  = (const float*)d_in[13];
    const float* bout  = (const float*)d_in[14];
    float* out = (float*)d_out;

    float *pw4, *pwr;
    unsigned *phall, *pwout;
    cudaGetSymbolAddress((void**)&pw4,   g_w4);
    cudaGetSymbolAddress((void**)&pwr,   g_wr);
    cudaGetSymbolAddress((void**)&phall, g_hall_tf);
    cudaGetSymbolAddress((void**)&pwout, g_wout_tf);

    static bool attr_done = false;
    if (!attr_done) {
        cudaFuncSetAttribute(gemm_tf32_v2,
                             cudaFuncAttributeMaxDynamicSharedMemorySize,
                             SMEM_UINTS * 4);
        attr_done = true;
    }

    // state init (h = enc, semaphores = 0)
    init_kernel<<<(BATCH*DD + 255) / 256, 256>>>(enc);

    // pre-convert W_out to tf32 bits
    wout_convert<<<(VV*DD/4 + 255) / 256, 256>>>(Wout);

    // precompute w4_all and wr_all
    {
        dim3 g1((G4 + TS - 1) / TS, (BATCH*TT + TS - 1) / TS);
        gemm_tn<true><<<g1, 256>>>(BATCH*TT, G4, DW, E, tgt, Ww2h, bw2h, pw4, G4);
        dim3 g2((AA + TS - 1) / TS, (BATCH*TT + TS - 1) / TS);
        gemm_tn<true><<<g2, 256>>>(BATCH*TT, AA, DW, E, tgt, Ww2hr, bw2hr, pwr, AA);
    }

    // whole recurrence in ONE persistent kernel (fence-free sync)
    recurrent_kernel<<<NBLK, NTHR>>>(Wh2h, bh2h, Wh2hr, bh2hr, Wdc, enc, act);

    // dominant output projection on tensor cores (tf32, pre-converted)
    {
        dim3 g3(VV / BN, (BATCH*TT + BM - 1) / BM);   // 125 x 14
        gemm_tf32_v2<<<g3, 256, SMEM_UINTS * 4>>>(BATCH*TT, phall, pwout,
                                                  bout, out, VV);
    }
}

// round 9
// speedup vs baseline: 2.3810x; 1.1908x over previous
#include <cuda_runtime.h>
#include <math.h>

// Problem constants
#define BATCH 32
#define TT 55
#define VV 32000
#define DW 256
#define DD 512
#define AA 200
#define G4 2048   // 4*D
#define NCOL (G4 + AA)   // 2248
#define WTS 2304         // padded row stride of transposed weights (128B-aligned)

#define NBLK 142   // persistent blocks
#define NTHR 256

// Scratch (device globals; no allocation allowed)
__device__ float    g_w4[BATCH*TT*G4];     // precomputed w4_all [b*T+t, 4D]
__device__ float    g_wr[BATCH*TT*AA];     // precomputed wr_all [b*T+t, A]
__device__ float    g_h[BATCH*DD];         // recurrent h state [B,D]
__device__ float    g_dt[BATCH*AA];        // dt state
__device__ float    g_gates[BATCH*G4];     // activated gates for current step
__device__ unsigned g_hall_tf[BATCH*TT*DD];// all h_t as tf32 bits
__device__ unsigned g_wout_tf[VV*DD];      // W_out as tf32 bits
__device__ float    g_wt[DD*WTS];          // [Wh2h ; Wh2hr] transposed: [k][col]
__device__ float    g_wdt[AA*DD];          // Wdc transposed: [a][j]
__device__ unsigned g_arrA;                // phase1-done arrivals
__device__ unsigned g_arrB;                // phase2-done arrivals

// ---------------------------------------------------------------------------
__device__ __forceinline__ unsigned tf32r(float x) {
    unsigned y;
    asm("cvt.rna.tf32.f32 %0, %1;" : "=r"(y) : "f"(x));
    return y;
}

__global__ void init_kernel(const float* __restrict__ enc) {
    int i = blockIdx.x * blockDim.x + threadIdx.x;
    if (i < BATCH*DD) g_h[i] = enc[i];
    if (i == 0) { g_arrA = 0u; g_arrB = 0u; }
}

__global__ void __launch_bounds__(256) wout_convert(const float* __restrict__ W) {
    int i = blockIdx.x * blockDim.x + threadIdx.x;
    const float4 v = ((const float4*)W)[i];
    uint4 o = make_uint4(tf32r(v.x), tf32r(v.y), tf32r(v.z), tf32r(v.w));
    ((uint4*)g_wout_tf)[i] = o;
}

// ---- one-time weight transposes (coalesced reads AND writes via smem) -----
__global__ void __launch_bounds__(256) transpose_w(
    const float* __restrict__ Wh2h, const float* __restrict__ Wh2hr)
{
    __shared__ float tile[32][33];
    const int ct = blockIdx.x;           // col tile (71 tiles covers 2272)
    const int kt = blockIdx.y;           // k tile (16)
    const int tx = threadIdx.x, ty = threadIdx.y;   // 32 x 8
    #pragma unroll
    for (int i = 0; i < 4; i++) {
        int col = ct*32 + ty + i*8;
        int k   = kt*32 + tx;
        float v = 0.f;
        if (col < G4)           v = Wh2h[(size_t)col*DD + k];
        else if (col < NCOL)    v = Wh2hr[(size_t)(col-G4)*DD + k];
        tile[ty + i*8][tx] = v;
    }
    __syncthreads();
    #pragma unroll
    for (int i = 0; i < 4; i++) {
        int k   = kt*32 + ty + i*8;
        int col = ct*32 + tx;
        g_wt[(size_t)k*WTS + col] = tile[tx][ty + i*8];
    }
}

__global__ void __launch_bounds__(256) transpose_wdc(const float* __restrict__ Wdc)
{
    __shared__ float tile[32][33];
    const int jt = blockIdx.x;           // 16 tiles over j (512)
    const int at = blockIdx.y;           // 7 tiles over a (224 >= 200)
    const int tx = threadIdx.x, ty = threadIdx.y;
    #pragma unroll
    for (int i = 0; i < 4; i++) {
        int j = jt*32 + ty + i*8;
        int a = at*32 + tx;
        tile[ty + i*8][tx] = (a < AA) ? Wdc[(size_t)j*AA + a] : 0.f;
    }
    __syncthreads();
    #pragma unroll
    for (int i = 0; i < 4; i++) {
        int a = at*32 + ty + i*8;
        int j = jt*32 + tx;
        if (a < AA) g_wdt[(size_t)a*DD + j] = tile[tx][ty + i*8];
    }
}

__device__ __forceinline__ float sigmoidf_(float x) {
    return 1.f / (1.f + expf(-x));
}

// Fence-free semaphores (no CCTL.IVALL; cross-CTA data read via __ldcg)
__device__ __forceinline__ void sem_arrive(unsigned* ctr) {
    __syncthreads();
    if (threadIdx.x == 0)
        asm volatile("red.release.gpu.global.add.u32 [%0], 1;"
                     :: "l"(ctr) : "memory");
}
__device__ __forceinline__ void sem_wait(unsigned* ctr, unsigned tgt) {
    if (threadIdx.x == 0) {
        unsigned v;
        do {
            asm volatile("ld.acquire.gpu.global.u32 %0, [%1];"
                         : "=r"(v) : "l"(ctr) : "memory");
        } while (v < tgt);
    }
    __syncthreads();
}

// ---------------------------------------------------------------------------
// Persistent recurrence kernel, coalesced-weight edition.
// Phase1: block=(colgroup32, batchhalf16); lane=col, warp=2 batches.
//   Weights read from g_wt[k][col]: warp LDG = 1 line, L1-resident.
//   h staged interleaved: smem_f[k*16 + w*2 + par] = h[bh*16+2w+par][k].
// Phase2: blocks 0..63; weights from g_wdt[a][j] coalesced; dt staged smem.
// ---------------------------------------------------------------------------
__global__ void __launch_bounds__(NTHR, 1) recurrent_kernel(
    const float* __restrict__ bh2h, const float* __restrict__ bh2hr,
    const float* __restrict__ enc,  const float* __restrict__ act)
{
    __shared__ float smem_f[16 * DD];    // 32 KB

    const int blk  = blockIdx.x;
    const int tid  = threadIdx.x;
    const int w    = tid >> 5;
    const int lane = tid & 31;

    const int  colg = blk >> 1;
    const int  bh   = blk & 1;
    const int  col  = colg * 32 + lane;
    const bool p1   = (col < NCOL);
    const int  b0   = bh * 16 + w * 2;
    const int  b1   = b0 + 1;

    float bias = 0.f;
    bool  is_r = false;
    int   acol = 0;
    if (p1) {
        if (col < G4) bias = bh2h[col];
        else { is_r = true; acol = col - G4; bias = bh2hr[acol]; }
    }
    float d0 = 0.f, d1 = 0.f;
    if (p1 && is_r) {
        d0 = __ldcg(act + b0 * AA + acol);
        d1 = __ldcg(act + b1 * AA + acol);
    }

    const bool p2 = (blk < 64);
    const int  colg2 = blk >> 2;
    const int  b2    = (blk & 3) * 8 + w;
    const int  j2    = colg2 * 32 + lane;
    float creg = 0.f;
    if (p2) creg = __ldcg(enc + b2 * DD + j2);

    unsigned* arrA; unsigned* arrB;
    asm("cvta.global.u64 %0, g_arrA;" : "=l"(arrA));
    asm("cvta.global.u64 %0, g_arrB;" : "=l"(arrB));

    const float* wt = g_wt + col;   // stride WTS per k (coalesced per warp)

    for (int t = 0; t < TT; t++) {
        // ---- wait until h(t) is ready ----
        sem_wait(arrB, 64u * (unsigned)t);

        // ---- stage h interleaved: smem_f[k*16 + w2*2 + par] ----
        {
            const float4* src = (const float4*)(g_h + bh * 16 * DD);
            #pragma unroll
            for (int i = 0; i < 8; i++) {
                int idx = i * NTHR + tid;         // 0..2047
                float4 v = __ldcg(src + idx);
                int b  = idx >> 7;                // 0..15
                int kq = idx & 127;
                int base = (kq * 4) * 16 + (b >> 1) * 2 + (b & 1);
                smem_f[base     ] = v.x;
                smem_f[base + 16] = v.y;
                smem_f[base + 32] = v.z;
                smem_f[base + 48] = v.w;
            }
        }
        __syncthreads();

        // ---- phase1 compute ----
        if (p1) {
            const float* hw = smem_f + w * 2;
            float acc0a = 0.f, acc0b = 0.f, acc1a = 0.f, acc1b = 0.f;
            #pragma unroll 8
            for (int k = 0; k < DD; k += 2) {
                float w0 = wt[(k    ) * WTS];
                float w1 = wt[(k + 1) * WTS];
                float2 hv0 = *(const float2*)(hw + (k    ) * 16);
                float2 hv1 = *(const float2*)(hw + (k + 1) * 16);
                acc0a += w0 * hv0.x; acc1a += w0 * hv0.y;
                acc0b += w1 * hv1.x; acc1b += w1 * hv1.y;
            }
            float acc0 = acc0a + acc0b;
            float acc1 = acc1a + acc1b;
            if (!is_r) {
                float v0 = g_w4[(size_t)(b0*TT + t) * G4 + col] + acc0 + bias;
                float v1 = g_w4[(size_t)(b1*TT + t) * G4 + col] + acc1 + bias;
                v0 = (col < 3*DD) ? sigmoidf_(v0) : tanhf(v0);
                v1 = (col < 3*DD) ? sigmoidf_(v1) : tanhf(v1);
                g_gates[b0 * G4 + col] = v0;
                g_gates[b1 * G4 + col] = v1;
            } else {
                float r0 = sigmoidf_(g_wr[(size_t)(b0*TT + t) * AA + acol] + acc0 + bias);
                float r1 = sigmoidf_(g_wr[(size_t)(b1*TT + t) * AA + acol] + acc1 + bias);
                d0 *= r0;
                d1 *= r1;
                g_dt[b0 * AA + acol] = d0;
                g_dt[b1 * AA + acol] = d1;
            }
        }

        // ---- announce phase1 done ----
        sem_arrive(arrA);

        // ---- phase2 on blocks 0..63 ----
        if (p2) {
            sem_wait(arrA, 142u * (unsigned)(t + 1));

            // stage this block's 8 dt rows (8*200 floats) into smem
            int bb = (blk & 3) * 8;
            for (int i = tid; i < 8 * AA; i += NTHR)
                smem_f[i] = __ldcg(g_dt + bb * AA + i);
            __syncthreads();

            const float* wdt = g_wdt + j2;        // stride DD per a (coalesced)
            const float* dts = smem_f + w * AA;   // uniform per warp
            float acc_a = 0.f, acc_b = 0.f;
            #pragma unroll 10
            for (int a = 0; a < AA; a += 2) {
                acc_a += dts[a    ] * wdt[(a    ) * DD];
                acc_b += dts[a + 1] * wdt[(a + 1) * DD];
            }
            float dtw = tanhf(acc_a + acc_b);
            float gi = __ldcg(g_gates + b2 * G4 + j2);
            float gf = __ldcg(g_gates + b2 * G4 + DD   + j2);
            float go = __ldcg(g_gates + b2 * G4 + 2*DD + j2);
            float ch = __ldcg(g_gates + b2 * G4 + 3*DD + j2);
            creg = gf * creg + gi * ch + dtw;
            float h = go * tanhf(creg);
            g_h[b2 * DD + j2] = h;
            g_hall_tf[(size_t)(b2 * TT + t) * DD + j2] = tf32r(h);

            sem_arrive(arrB);
        }
    }
}

// ---------------------------------------------------------------------------
// fp32 tiled GEMM (two small precompute GEMMs)
// ---------------------------------------------------------------------------
#define TS 128
#define KT 8

template<bool GATHER>
__global__ void __launch_bounds__(256) gemm_tn(
    int M, int N, int K,
    const float* __restrict__ A, const int* __restrict__ idx,
    const float* __restrict__ B,
    const float* __restrict__ bias,
    float* __restrict__ C, int ldc)
{
    __shared__ float As[KT][TS];
    __shared__ float Bs[KT][TS];

    int tid = threadIdx.x;
    int lrow = tid >> 1;
    int kc   = (tid & 1) * 4;

    int gm_l = blockIdx.y * TS + lrow;
    int gn_l = blockIdx.x * TS + lrow;

    const float* aptr = nullptr;
    if (gm_l < M) {
        int ar = GATHER ? idx[gm_l] : gm_l;
        aptr = A + (size_t)ar * K;
    }
    const float* bptr = (gn_l < N) ? (B + (size_t)gn_l * K) : nullptr;

    int tx = tid & 15;
    int ty = tid >> 4;

    float acc[8][8];
    #pragma unroll
    for (int i = 0; i < 8; i++)
        #pragma unroll
        for (int j = 0; j < 8; j++) acc[i][j] = 0.f;

    for (int k0 = 0; k0 < K; k0 += KT) {
        float4 av = make_float4(0.f, 0.f, 0.f, 0.f);
        float4 bv = make_float4(0.f, 0.f, 0.f, 0.f);
        if (aptr) av = *(const float4*)(aptr + k0 + kc);
        if (bptr) bv = *(const float4*)(bptr + k0 + kc);
        __syncthreads();
        As[kc+0][lrow] = av.x; As[kc+1][lrow] = av.y;
        As[kc+2][lrow] = av.z; As[kc+3][lrow] = av.w;
        Bs[kc+0][lrow] = bv.x; Bs[kc+1][lrow] = bv.y;
        Bs[kc+2][lrow] = bv.z; Bs[kc+3][lrow] = bv.w;
        __syncthreads();
        #pragma unroll
        for (int kk = 0; kk < KT; kk++) {
            float4 a0 = *(const float4*)&As[kk][ty*8];
            float4 a1 = *(const float4*)&As[kk][ty*8+4];
            float4 b0 = *(const float4*)&Bs[kk][tx*8];
            float4 b1 = *(const float4*)&Bs[kk][tx*8+4];
            float a[8] = {a0.x,a0.y,a0.z,a0.w,a1.x,a1.y,a1.z,a1.w};
            float b[8] = {b0.x,b0.y,b0.z,b0.w,b1.x,b1.y,b1.z,b1.w};
            #pragma unroll
            for (int i = 0; i < 8; i++)
                #pragma unroll
                for (int j = 0; j < 8; j++)
                    acc[i][j] += a[i] * b[j];
        }
    }

    #pragma unroll
    for (int i = 0; i < 8; i++) {
        int gm = blockIdx.y * TS + ty*8 + i;
        if (gm < M) {
            #pragma unroll
            for (int j = 0; j < 8; j += 4) {
                int gn = blockIdx.x * TS + tx*8 + j;
                if (gn < N) {
                    float4 bs = *(const float4*)(bias + gn);
                    float4 o;
                    o.x = acc[i][j+0] + bs.x;
                    o.y = acc[i][j+1] + bs.y;
                    o.z = acc[i][j+2] + bs.z;
                    o.w = acc[i][j+3] + bs.w;
                    *(float4*)(C + (size_t)gm * ldc + gn) = o;
                }
            }
        }
    }
}

// ---------------------------------------------------------------------------
// tf32 tensor-core GEMM v2 (unchanged — measured win)
// ---------------------------------------------------------------------------
#define BM 128
#define BN 256
#define BK 32
#define NSTAGE 3
#define A_STAGE (BM*BK)
#define B_STAGE (BN*BK)
#define SMEM_UINTS (NSTAGE*(A_STAGE+B_STAGE))   // 144KB

__device__ __forceinline__ void mma_tf32(float c[4],
    unsigned a0, unsigned a1, unsigned a2, unsigned a3,
    unsigned b0, unsigned b1)
{
    asm volatile(
        "mma.sync.aligned.m16n8k8.row.col.f32.tf32.tf32.f32 "
        "{%0,%1,%2,%3}, {%4,%5,%6,%7}, {%8,%9}, {%0,%1,%2,%3};\n"
        : "+f"(c[0]), "+f"(c[1]), "+f"(c[2]), "+f"(c[3])
        : "r"(a0), "r"(a1), "r"(a2), "r"(a3), "r"(b0), "r"(b1));
}

__device__ __forceinline__ void cpasync16(unsigned saddr, const void* gptr) {
    asm volatile("cp.async.cg.shared.global [%0], [%1], 16;"
                 :: "r"(saddr), "l"(gptr));
}

__global__ void __launch_bounds__(256, 1) gemm_tf32_v2(
    int M,
    const unsigned* __restrict__ A,
    const unsigned* __restrict__ B,
    const float* __restrict__ bias,
    float* __restrict__ C, int ldc)
{
    extern __shared__ unsigned smem_u[];

    const int tid  = threadIdx.x;
    const int lane = tid & 31;
    const int w    = tid >> 5;
    const int wm   = (w & 1) * 64;
    const int wn   = (w >> 1) * 64;
    const int g8   = lane >> 2;
    const int tq   = lane & 3;

    const int bM = blockIdx.y * BM;
    const int bN = blockIdx.x * BN;

    const int lf   = tid & 7;
    const int lrow = tid >> 3;

    const unsigned smem_base = (unsigned)__cvta_generic_to_shared(smem_u);

    float acc[4][8][4];
    #pragma unroll
    for (int mi = 0; mi < 4; mi++)
        #pragma unroll
        for (int ni = 0; ni < 8; ni++)
            #pragma unroll
            for (int q = 0; q < 4; q++) acc[mi][ni][q] = 0.f;

    const int NKT = DD / BK;   // 16

    auto load_tile = [&](int st, int kt) {
        const unsigned aoff = smem_base + (st * A_STAGE) * 4u;
        const unsigned boff = smem_base + (NSTAGE * A_STAGE + st * B_STAGE) * 4u;
        #pragma unroll
        for (int i = 0; i < 4; i++) {
            int r = lrow + 32*i;
            int gr = bM + r; if (gr >= M) gr = M - 1;
            int ch = lf ^ (r & 7);
            cpasync16(aoff + (r*BK + ch*4) * 4u,
                      A + (size_t)gr * DD + (size_t)kt*BK + lf*4);
        }
        #pragma unroll
        for (int i = 0; i < 8; i++) {
            int r = lrow + 32*i;
            int gn = bN + r;
            int ch = lf ^ (r & 7);
            cpasync16(boff + (r*BK + ch*4) * 4u,
                      B + (size_t)gn * DD + (size_t)kt*BK + lf*4);
        }
    };

    #pragma unroll
    for (int st = 0; st < NSTAGE; st++) {
        load_tile(st, st);
        asm volatile("cp.async.commit_group;");
    }

    for (int kt = 0; kt < NKT; kt++) {
        asm volatile("cp.async.wait_group %0;" :: "n"(NSTAGE - 1));
        __syncthreads();

        const int st = kt % NSTAGE;
        const unsigned* sA = smem_u + st * A_STAGE;
        const unsigned* sB = smem_u + NSTAGE * A_STAGE + st * B_STAGE;

        #pragma unroll
        for (int s = 0; s < 4; s++) {
            const int c0 = s*2;
            const int c1 = s*2 + 1;
            unsigned af[4][4];
            #pragma unroll
            for (int mi = 0; mi < 4; mi++) {
                int r0 = wm + mi*16 + g8;
                int r1 = r0 + 8;
                af[mi][0] = sA[r0*BK + ((c0 ^ (r0 & 7))*4 + tq)];
                af[mi][1] = sA[r1*BK + ((c0 ^ (r1 & 7))*4 + tq)];
                af[mi][2] = sA[r0*BK + ((c1 ^ (r0 & 7))*4 + tq)];
                af[mi][3] = sA[r1*BK + ((c1 ^ (r1 & 7))*4 + tq)];
            }
            unsigned bf[8][2];
            #pragma unroll
            for (int ni = 0; ni < 8; ni++) {
                int n0 = wn + ni*8 + g8;
                bf[ni][0] = sB[n0*BK + ((c0 ^ (n0 & 7))*4 + tq)];
                bf[ni][1] = sB[n0*BK + ((c1 ^ (n0 & 7))*4 + tq)];
            }
            #pragma unroll
            for (int mi = 0; mi < 4; mi++)
                #pragma unroll
                for (int ni = 0; ni < 8; ni++)
                    mma_tf32(acc[mi][ni], af[mi][0], af[mi][1], af[mi][2],
                             af[mi][3], bf[ni][0], bf[ni][1]);
        }

        __syncthreads();
        if (kt + NSTAGE < NKT) load_tile(st, kt + NSTAGE);
        asm volatile("cp.async.commit_group;");
    }

    #pragma unroll
    for (int mi = 0; mi < 4; mi++) {
        int gm0 = bM + wm + mi*16 + g8;
        int gm1 = gm0 + 8;
        #pragma unroll
        for (int ni = 0; ni < 8; ni++) {
            int gn = bN + wn + ni*8 + tq*2;
            float2 bs = *(const float2*)(bias + gn);
            if (gm0 < M) {
                float2 o0; o0.x = acc[mi][ni][0] + bs.x; o0.y = acc[mi][ni][1] + bs.y;
                *(float2*)(C + (size_t)gm0 * ldc + gn) = o0;
            }
            if (gm1 < M) {
                float2 o1; o1.x = acc[mi][ni][2] + bs.x; o1.y = acc[mi][ni][3] + bs.y;
                *(float2*)(C + (size_t)gm1 * ldc + gn) = o1;
            }
        }
    }
}

// ---------------------------------------------------------------------------
// Launch
// ---------------------------------------------------------------------------
extern "C" void kernel_launch(void* const* d_in, const int* in_sizes, int n_in,
                              void* d_out, int out_size) {
    const int*   tgt   = (const int*)  d_in[0];
    const float* enc   = (const float*)d_in[1];
    const float* act   = (const float*)d_in[2];
    const float* E     = (const float*)d_in[3];
    const float* Ww2h  = (const float*)d_in[4];
    const float* bw2h  = (const float*)d_in[5];
    const float* Wh2h  = (const float*)d_in[6];
    const float* bh2h  = (const float*)d_in[7];
    const float* Ww2hr = (const float*)d_in[8];
    const float* bw2hr = (const float*)d_in[9];
    const float* Wh2hr = (const float*)d_in[10];
    const float* bh2hr = (const float*)d_in[11];
    const float* Wdc   = (const float*)d_in[12];
    const float* Wout  = (const float*)d_in[13];
    const float* bout  = (const float*)d_in[14];
    float* out = (float*)d_out;

    float *pw4, *pwr;
    unsigned *phall, *pwout;
    cudaGetSymbolAddress((void**)&pw4,   g_w4);
    cudaGetSymbolAddress((void**)&pwr,   g_wr);
    cudaGetSymbolAddress((void**)&phall, g_hall_tf);
    cudaGetSymbolAddress((void**)&pwout, g_wout_tf);

    static bool attr_done = false;
    if (!attr_done) {
        cudaFuncSetAttribute(gemm_tf32_v2,
                             cudaFuncAttributeMaxDynamicSharedMemorySize,
                             SMEM_UINTS * 4);
        attr_done = true;
    }

    // state init (h = enc, semaphores = 0)
    init_kernel<<<(BATCH*DD + 255) / 256, 256>>>(enc);

    // one-time weight transposes (independent of everything else)
    transpose_w<<<dim3(71, 16), dim3(32, 8)>>>(Wh2h, Wh2hr);
    transpose_wdc<<<dim3(16, 7), dim3(32, 8)>>>(Wdc);

    // pre-convert W_out to tf32 bits
    wout_convert<<<(VV*DD/4 + 255) / 256, 256>>>(Wout);

    // precompute w4_all and wr_all
    {
        dim3 g1((G4 + TS - 1) / TS, (BATCH*TT + TS - 1) / TS);
        gemm_tn<true><<<g1, 256>>>(BATCH*TT, G4, DW, E, tgt, Ww2h, bw2h, pw4, G4);
        dim3 g2((AA + TS - 1) / TS, (BATCH*TT + TS - 1) / TS);
        gemm_tn<true><<<g2, 256>>>(BATCH*TT, AA, DW, E, tgt, Ww2hr, bw2hr, pwr, AA);
    }

    // whole recurrence in ONE persistent kernel (coalesced weights)
    recurrent_kernel<<<NBLK, NTHR>>>(bh2h, bh2hr, enc, act);

    // dominant output projection on tensor cores
    {
        dim3 g3(VV / BN, (BATCH*TT + BM - 1) / BM);   // 125 x 14
        gemm_tf32_v2<<<g3, 256, SMEM_UINTS * 4>>>(BATCH*TT, phall, pwout,
                                                  bout, out, VV);
    }
}